// round 11
// baseline (speedup 1.0000x reference)
#include <cuda_runtime.h>
#include <cuda_fp16.h>
#include <cstdint>
#include <math.h>

#define BATCH   4096
#define IDIM    1024
#define LDIM    1024
#define HDIM    2048
#define ODIM    512
#define HALTH   1024
#define OUTER   8
#define INNER   4
#define JDIM    (LDIM + ODIM)    // 1536
#define H12     (HDIM + HALTH)   // 3072

// ---------------------------------------------------------------------------
// Device-global scratch (no allocation allowed)
// ---------------------------------------------------------------------------
__device__ float  g_stateA[BATCH * LDIM];
__device__ float  g_stateB[BATCH * LDIM];
__device__ float  g_xgbase[BATCH * 3 * LDIM];

__device__ __half g_xg16[BATCH * 3 * LDIM];
__device__ __half g_h1216[BATCH * H12];      // [h1 (2048) | h2 (1024)] per row

__device__ __half g_state16A[BATCH * LDIM];
__device__ __half g_state16B[BATCH * LDIM];
__device__ __half g_ans16[BATCH * ODIM];
__device__ __half g_in16[BATCH * IDIM];

__device__ __half g_wih16[3 * LDIM * JDIM];
__device__ __half g_whh16[3 * LDIM * LDIM];
__device__ __half g_aw116[HDIM * JDIM];
__device__ __half g_aw216[ODIM * HDIM];
__device__ __half g_hw116[HALTH * JDIM];

__device__ __forceinline__ uint32_t smem_u32(const void* p) {
    uint32_t a;
    asm("{ .reg .u64 t; cvta.to.shared.u64 t, %1; cvt.u32.u64 %0, t; }" : "=r"(a) : "l"(p));
    return a;
}

// Swizzled smem layout for a 32-half (64B) column block packed as 128B lines.
// 16B-unit offset for (row r, 16B-chunk c in 0..3). Conflict-free for both
// cp.async fill and ldmatrix reads (validated rounds 4-10).
__device__ __forceinline__ uint32_t soff(int r, int c) {
    return (uint32_t)((((r >> 1) * 8) + ((((r & 1) << 2) | c) ^ ((r >> 1) & 7))) << 4);
}
// BK=64 stage: two 32-col blocks, block1 at +rows*64 bytes. cc in 0..7.
__device__ __forceinline__ uint32_t soff64(int r, int cc, int rows) {
    return (cc < 4) ? soff(r, cc) : (uint32_t)(rows * 64) + soff(r, cc - 4);
}

// ---------------------------------------------------------------------------
// Generic fp16 tensor-core GEMM (256 threads, 2 CTAs/SM, BK=64, 3 stages):
//   C = act( concat(A1,A2) @ concatN(W1,W2)^T + biasSel|C0 )
//   Requires K % 64 == 0 and K1 % 64 == 0.
// ---------------------------------------------------------------------------
template <int WM, int WN, int MI, int NG, int W32, int W16, int ACT, int ADDC>
__global__ void __launch_bounds__(WM * WN * 32, 2)
hgemm(const __half* __restrict__ A1, int lda1, int K1,
      const __half* __restrict__ A2, int lda2,
      const __half* __restrict__ W1, const __half* __restrict__ W2,
      int ldw, int nsplit,
      const float* __restrict__ bias1, const float* __restrict__ bias2,
      const float* __restrict__ C0,
      float* __restrict__ C,
      __half* __restrict__ C2,
      int N, int K)
{
    constexpr int THREADS = WM * WN * 32;
    constexpr int BM      = WM * MI * 16;
    constexpr int BN      = WN * NG * 16;
    constexpr int NI      = 2 * NG;
    constexpr int STAGE   = (BM + BN) * 128;              // bytes (BK=64)
    constexpr int NLOAD   = (BM + BN) * 8 / THREADS;      // 16B chunks/thread

    extern __shared__ __align__(128) char smem[];
    const uint32_t sb = smem_u32(smem);

    const int tid  = threadIdx.x;
    const int lane = tid & 31;
    const int warp = tid >> 5;
    const int wm   = warp / WN;
    const int wn   = warp % WN;
    const int row0 = blockIdx.y * BM;
    const int col0 = blockIdx.x * BN;

    float c[MI][NI][4];
#pragma unroll
    for (int i = 0; i < MI; i++)
#pragma unroll
        for (int j = 0; j < NI; j++)
#pragma unroll
            for (int k = 0; k < 4; k++) c[i][j][k] = 0.0f;

    const int nc = K >> 6;

    auto load_chunk = [&](int t) {
        const int st = t % 3;
        const int k0 = t << 6;
        const __half* Ab;
        int lda;
        if (k0 < K1) { Ab = A1 + k0;        lda = lda1; }
        else         { Ab = A2 + (k0 - K1); lda = lda2; }
        const uint32_t aB = sb + st * STAGE;
        const uint32_t bB = aB + BM * 128;
#pragma unroll
        for (int j = 0; j < NLOAD; j++) {
            const int idx = j * THREADS + tid;
            if (idx < BM * 8) {
                const int r = idx >> 3, cc = idx & 7;
                const uint32_t d = aB + soff64(r, cc, BM);
                const __half* g = Ab + (size_t)(row0 + r) * lda + cc * 8;
                asm volatile("cp.async.cg.shared.global [%0], [%1], 16;" :: "r"(d), "l"(g));
            } else {
                const int li = idx - BM * 8;
                const int r = li >> 3, cc = li & 7;
                const int wr = col0 + r;
                const __half* wbase = (wr < nsplit) ? (W1 + (size_t)wr * ldw)
                                                    : (W2 + (size_t)(wr - nsplit) * ldw);
                const uint32_t d = bB + soff64(r, cc, BN);
                asm volatile("cp.async.cg.shared.global [%0], [%1], 16;"
                             :: "r"(d), "l"(wbase + k0 + cc * 8));
            }
        }
        asm volatile("cp.async.commit_group;");
    };

    load_chunk(0);
    load_chunk(1);

    for (int t = 0; t < nc; t++) {
        if (t + 2 <= nc) asm volatile("cp.async.wait_group 1;");
        else             asm volatile("cp.async.wait_group 0;");
        __syncthreads();
        if (t + 2 < nc) load_chunk(t + 2);

        const uint32_t aB = sb + (t % 3) * STAGE;
        const uint32_t bB = aB + BM * 128;

#pragma unroll
        for (int kh = 0; kh < 4; kh++) {
            const uint32_t aBlk = aB + ((kh >> 1) ? BM * 64 : 0);
            const uint32_t bBlk = bB + ((kh >> 1) ? BN * 64 : 0);
            uint32_t a[MI][4];
#pragma unroll
            for (int mi = 0; mi < MI; mi++) {
                const int row = wm * (16 * MI) + mi * 16 + (lane & 15);
                const int cc  = (kh & 1) * 2 + (lane >> 4);
                asm volatile("ldmatrix.sync.aligned.m8n8.x4.shared.b16 {%0,%1,%2,%3}, [%4];"
                             : "=r"(a[mi][0]), "=r"(a[mi][1]), "=r"(a[mi][2]), "=r"(a[mi][3])
                             : "r"(aBlk + soff(row, cc)));
            }
            uint32_t b[NG][4];
#pragma unroll
            for (int ng = 0; ng < NG; ng++) {
                const int row = wn * (16 * NG) + ng * 16 + (lane & 7) + ((lane >> 4) << 3);
                const int cc  = (kh & 1) * 2 + ((lane >> 3) & 1);
                asm volatile("ldmatrix.sync.aligned.m8n8.x4.shared.b16 {%0,%1,%2,%3}, [%4];"
                             : "=r"(b[ng][0]), "=r"(b[ng][1]), "=r"(b[ng][2]), "=r"(b[ng][3])
                             : "r"(bBlk + soff(row, cc)));
            }
#pragma unroll
            for (int mi = 0; mi < MI; mi++)
#pragma unroll
                for (int ng = 0; ng < NG; ng++) {
                    asm volatile(
                        "mma.sync.aligned.m16n8k16.row.col.f32.f16.f16.f32 "
                        "{%0,%1,%2,%3},{%4,%5,%6,%7},{%8,%9},{%0,%1,%2,%3};"
                        : "+f"(c[mi][2 * ng][0]), "+f"(c[mi][2 * ng][1]),
                          "+f"(c[mi][2 * ng][2]), "+f"(c[mi][2 * ng][3])
                        : "r"(a[mi][0]), "r"(a[mi][1]), "r"(a[mi][2]), "r"(a[mi][3]),
                          "r"(b[ng][0]), "r"(b[ng][1]));
                    asm volatile(
                        "mma.sync.aligned.m16n8k16.row.col.f32.f16.f16.f32 "
                        "{%0,%1,%2,%3},{%4,%5,%6,%7},{%8,%9},{%0,%1,%2,%3};"
                        : "+f"(c[mi][2 * ng + 1][0]), "+f"(c[mi][2 * ng + 1][1]),
                          "+f"(c[mi][2 * ng + 1][2]), "+f"(c[mi][2 * ng + 1][3])
                        : "r"(a[mi][0]), "r"(a[mi][1]), "r"(a[mi][2]), "r"(a[mi][3]),
                          "r"(b[ng][2]), "r"(b[ng][3]));
                }
        }
    }

    // Epilogue
#pragma unroll
    for (int mi = 0; mi < MI; mi++) {
        const int r0 = row0 + wm * (16 * MI) + mi * 16 + (lane >> 2);
#pragma unroll
        for (int ni = 0; ni < NI; ni++) {
            const int col = col0 + wn * (16 * NG) + ni * 8 + (lane & 3) * 2;
            const size_t i0 = (size_t)r0 * N + col;
            const size_t i1 = (size_t)(r0 + 8) * N + col;
            float v00, v01, v10, v11;
            if (ADDC) {
                const float2 a0 = *(const float2*)&C0[i0];
                const float2 a1 = *(const float2*)&C0[i1];
                v00 = c[mi][ni][0] + a0.x; v01 = c[mi][ni][1] + a0.y;
                v10 = c[mi][ni][2] + a1.x; v11 = c[mi][ni][3] + a1.y;
            } else {
                const float* bp = (col < nsplit) ? (bias1 + col) : (bias2 + col - nsplit);
                const float b0 = __ldg(bp);
                const float b1 = __ldg(bp + 1);
                v00 = c[mi][ni][0] + b0; v01 = c[mi][ni][1] + b1;
                v10 = c[mi][ni][2] + b0; v11 = c[mi][ni][3] + b1;
            }
            if (ACT == 1) {
                v00 = fmaxf(v00, 0.0f); v01 = fmaxf(v01, 0.0f);
                v10 = fmaxf(v10, 0.0f); v11 = fmaxf(v11, 0.0f);
            }
            if (W32) {
                C[i0] = v00; C[i0 + 1] = v01;
                C[i1] = v10; C[i1 + 1] = v11;
            }
            if (W16) {
                float w00 = v00, w01 = v01, w10 = v10, w11 = v11;
                if (ACT == 2) {
                    w00 = tanhf(v00); w01 = tanhf(v01);
                    w10 = tanhf(v10); w11 = tanhf(v11);
                }
                *(__half2*)&C2[i0] = __floats2half2_rn(w00, w01);
                *(__half2*)&C2[i1] = __floats2half2_rn(w10, w11);
            }
        }
    }
}

// ---------------------------------------------------------------------------
// Fused GRU GEMM, double-buffered state, 256 threads (2 CTAs/SM),
// BK=64 chunks, 3-stage pipeline. BM=128 (WM=4, MI=2), BN=96 (WN=2, NG=3).
// Gate interleave: B-tile row rb -> weight row gate*L + j; accumulators
// (p, 2+p, 4+p) hold (r,z,n) of the same j.
// ---------------------------------------------------------------------------
__global__ void __launch_bounds__(256, 2)
gru_gemm(const float* __restrict__ bhh,
         const __half* __restrict__ s16in,
         const float* __restrict__ s32in,
         __half* __restrict__ s16out,
         float* __restrict__ s32out)
{
    constexpr int STAGE = (128 + 96) * 128;   // 28672 B

    extern __shared__ __align__(128) char smem[];
    const uint32_t sb = smem_u32(smem);

    const int tid  = threadIdx.x;
    const int lane = tid & 31;
    const int warp = tid >> 5;
    const int wm   = warp >> 1;   // 0..3
    const int wn   = warp & 1;    // 0..1
    const int row0 = blockIdx.y * 128;
    const int c0j  = blockIdx.x * 32;  // 32 j's per CTA

    float c[2][6][4];
#pragma unroll
    for (int i = 0; i < 2; i++)
#pragma unroll
        for (int j = 0; j < 6; j++)
#pragma unroll
            for (int k = 0; k < 4; k++) c[i][j][k] = 0.0f;

    auto load_chunk = [&](int t) {
        const int st = t % 3;
        const int k0 = t << 6;
        const uint32_t aB = sb + st * STAGE;
        const uint32_t bB = aB + 128 * 128;
#pragma unroll
        for (int j = 0; j < 7; j++) {             // (128+96)*8/256 = 7
            const int idx = j * 256 + tid;
            if (idx < 1024) {                     // A: 128 rows x 8 chunks
                const int r = idx >> 3, cc = idx & 7;
                const uint32_t d = aB + soff64(r, cc, 128);
                const __half* g = s16in + (size_t)(row0 + r) * LDIM + k0 + cc * 8;
                asm volatile("cp.async.cg.shared.global [%0], [%1], 16;" :: "r"(d), "l"(g));
            } else {                              // B: 96 rows x 8 chunks
                const int li = idx - 1024;
                const int rb = li >> 3, cc = li & 7;
                const int within = rb % 48;
                const int wrow = (within >> 4) * LDIM + c0j + (rb / 48) * 16 + (within & 15);
                const uint32_t d = bB + soff64(rb, cc, 96);
                const __half* g = g_whh16 + (size_t)wrow * LDIM + k0 + cc * 8;
                asm volatile("cp.async.cg.shared.global [%0], [%1], 16;" :: "r"(d), "l"(g));
            }
        }
        asm volatile("cp.async.commit_group;");
    };

    load_chunk(0);
    load_chunk(1);

    const int nc = LDIM >> 6;  // 16
    for (int t = 0; t < nc; t++) {
        if (t + 2 <= nc) asm volatile("cp.async.wait_group 1;");
        else             asm volatile("cp.async.wait_group 0;");
        __syncthreads();
        if (t + 2 < nc) load_chunk(t + 2);

        const uint32_t aB = sb + (t % 3) * STAGE;
        const uint32_t bB = aB + 128 * 128;

#pragma unroll
        for (int kh = 0; kh < 4; kh++) {
            const uint32_t aBlk = aB + ((kh >> 1) ? 128 * 64 : 0);
            const uint32_t bBlk = bB + ((kh >> 1) ? 96 * 64 : 0);
            uint32_t a[2][4];
#pragma unroll
            for (int mi = 0; mi < 2; mi++) {
                const int row = wm * 32 + mi * 16 + (lane & 15);
                const int cc  = (kh & 1) * 2 + (lane >> 4);
                asm volatile("ldmatrix.sync.aligned.m8n8.x4.shared.b16 {%0,%1,%2,%3}, [%4];"
                             : "=r"(a[mi][0]), "=r"(a[mi][1]), "=r"(a[mi][2]), "=r"(a[mi][3])
                             : "r"(aBlk + soff(row, cc)));
            }
            uint32_t b[3][4];
#pragma unroll
            for (int ng = 0; ng < 3; ng++) {
                const int row = wn * 48 + ng * 16 + (lane & 7) + ((lane >> 4) << 3);
                const int cc  = (kh & 1) * 2 + ((lane >> 3) & 1);
                asm volatile("ldmatrix.sync.aligned.m8n8.x4.shared.b16 {%0,%1,%2,%3}, [%4];"
                             : "=r"(b[ng][0]), "=r"(b[ng][1]), "=r"(b[ng][2]), "=r"(b[ng][3])
                             : "r"(bBlk + soff(row, cc)));
            }
#pragma unroll
            for (int mi = 0; mi < 2; mi++)
#pragma unroll
                for (int ng = 0; ng < 3; ng++) {
                    asm volatile(
                        "mma.sync.aligned.m16n8k16.row.col.f32.f16.f16.f32 "
                        "{%0,%1,%2,%3},{%4,%5,%6,%7},{%8,%9},{%0,%1,%2,%3};"
                        : "+f"(c[mi][2 * ng][0]), "+f"(c[mi][2 * ng][1]),
                          "+f"(c[mi][2 * ng][2]), "+f"(c[mi][2 * ng][3])
                        : "r"(a[mi][0]), "r"(a[mi][1]), "r"(a[mi][2]), "r"(a[mi][3]),
                          "r"(b[ng][0]), "r"(b[ng][1]));
                    asm volatile(
                        "mma.sync.aligned.m16n8k16.row.col.f32.f16.f16.f32 "
                        "{%0,%1,%2,%3},{%4,%5,%6,%7},{%8,%9},{%0,%1,%2,%3};"
                        : "+f"(c[mi][2 * ng + 1][0]), "+f"(c[mi][2 * ng + 1][1]),
                          "+f"(c[mi][2 * ng + 1][2]), "+f"(c[mi][2 * ng + 1][3])
                        : "r"(a[mi][0]), "r"(a[mi][1]), "r"(a[mi][2]), "r"(a[mi][3]),
                          "r"(b[ng][2]), "r"(b[ng][3]));
                }
        }
    }

    // Fused GRU epilogue: warp-tile cols = [r 0..15 | z 16..31 | n 32..47]
#pragma unroll
    for (int mi = 0; mi < 2; mi++) {
        const int r0 = row0 + wm * 32 + mi * 16 + (lane >> 2);
#pragma unroll
        for (int p = 0; p < 2; p++) {
            const int j0 = c0j + wn * 16 + p * 8 + (lane & 3) * 2;
            const float2 br = *(const float2*)&bhh[j0];
            const float2 bz = *(const float2*)&bhh[LDIM + j0];
            const float2 bn = *(const float2*)&bhh[2 * LDIM + j0];
            const float* cr = c[mi][p];
            const float* cz = c[mi][2 + p];
            const float* cn = c[mi][4 + p];
#pragma unroll
            for (int h = 0; h < 2; h++) {
                const int row = r0 + h * 8;
                const float hr0 = cr[2 * h] + br.x, hr1 = cr[2 * h + 1] + br.y;
                const float hz0 = cz[2 * h] + bz.x, hz1 = cz[2 * h + 1] + bz.y;
                const float hn0 = cn[2 * h] + bn.x, hn1 = cn[2 * h + 1] + bn.y;
                const size_t xb = (size_t)row * (3 * LDIM) + j0;
                const float2 xr = __half22float2(*(const __half2*)&g_xg16[xb]);
                const float2 xz = __half22float2(*(const __half2*)&g_xg16[xb + LDIM]);
                const float2 xn = __half22float2(*(const __half2*)&g_xg16[xb + 2 * LDIM]);
                const size_t si = (size_t)row * LDIM + j0;
                const float2 s = *(const float2*)&s32in[si];

                const float rr0 = 1.0f / (1.0f + expf(-(xr.x + hr0)));
                const float zz0 = 1.0f / (1.0f + expf(-(xz.x + hz0)));
                const float nn0 = tanhf(xn.x + rr0 * hn0);
                const float rr1 = 1.0f / (1.0f + expf(-(xr.y + hr1)));
                const float zz1 = 1.0f / (1.0f + expf(-(xz.y + hz1)));
                const float nn1 = tanhf(xn.y + rr1 * hn1);

                float2 ns;
                ns.x = (1.0f - zz0) * nn0 + zz0 * s.x;
                ns.y = (1.0f - zz1) * nn1 + zz1 * s.y;
                *(float2*)&s32out[si] = ns;
                *(__half2*)&s16out[si] = __floats2half2_rn(ns.x, ns.y);
            }
        }
    }
}

// ---------------------------------------------------------------------------
// One-shot init: fp16 conversions of all params + zero state/ans buffers.
// ---------------------------------------------------------------------------
#define N_IN   (BATCH * IDIM)
#define N_WIH  (3 * LDIM * JDIM)
#define N_WHH  (3 * LDIM * LDIM)
#define N_AW1  (HDIM * JDIM)
#define N_AW2  (ODIM * HDIM)
#define N_HW1  (HALTH * JDIM)
#define N_ZERO (BATCH * LDIM)
#define O1 N_IN
#define O2 (O1 + N_WIH)
#define O3 (O2 + N_WHH)
#define O4 (O3 + N_AW1)
#define O5 (O4 + N_AW2)
#define O6 (O5 + N_HW1)
#define O7 (O6 + N_ZERO)                 // 22020352 = 86017 * 256

__global__ void init_cvt(const float* __restrict__ inputs,
                         const float* __restrict__ W_ih,
                         const float* __restrict__ W_hh,
                         const float* __restrict__ aw1,
                         const float* __restrict__ aw2,
                         const float* __restrict__ hw1)
{
    const int i = blockIdx.x * blockDim.x + threadIdx.x;
    if (i < O1)      g_in16[i]         = __float2half_rn(inputs[i]);
    else if (i < O2) g_wih16[i - O1]   = __float2half_rn(W_ih[i - O1]);
    else if (i < O3) g_whh16[i - O2]   = __float2half_rn(W_hh[i - O2]);
    else if (i < O4) g_aw116[i - O3]   = __float2half_rn(aw1[i - O3]);
    else if (i < O5) g_aw216[i - O4]   = __float2half_rn(aw2[i - O4]);
    else if (i < O6) g_hw116[i - O5]   = __float2half_rn(hw1[i - O5]);
    else {
        const int j = i - O6;
        g_stateA[j]   = 0.0f;
        g_state16A[j] = __ushort_as_half((unsigned short)0);
        if (j < BATCH * ODIM) g_ans16[j] = __ushort_as_half((unsigned short)0);
    }
}

// ---------------------------------------------------------------------------
// Halt head: reads h2 slice of the merged h12 buffer.
// ---------------------------------------------------------------------------
__global__ void halt_kernel(const float* __restrict__ hw2,
                            const float* __restrict__ hb2,
                            float* __restrict__ out)
{
    const int row  = blockIdx.x * (blockDim.x >> 5) + (threadIdx.x >> 5);
    const int lane = threadIdx.x & 31;
    const __half2* h = (const __half2*)(g_h1216 + (size_t)row * H12 + HDIM);
    const float2* w0 = (const float2*)hw2;
    const float2* w1 = (const float2*)(hw2 + HALTH);
    float s0 = 0.0f, s1 = 0.0f;
    for (int k = lane; k < HALTH / 2; k += 32) {
        const float2 v  = __half22float2(h[k]);
        const float2 a0 = w0[k];
        const float2 a1 = w1[k];
        s0 += v.x * a0.x + v.y * a0.y;
        s1 += v.x * a1.x + v.y * a1.y;
    }
#pragma unroll
    for (int o = 16; o > 0; o >>= 1) {
        s0 += __shfl_down_sync(0xFFFFFFFFu, s0, o);
        s1 += __shfl_down_sync(0xFFFFFFFFu, s1, o);
    }
    if (lane == 0) {
        out[(size_t)row * 2]     = s0 + hb2[0];
        out[(size_t)row * 2 + 1] = s1 + hb2[1];
    }
}

// ---------------------------------------------------------------------------
// Host orchestration
// ---------------------------------------------------------------------------
extern "C" void kernel_launch(void* const* d_in, const int* in_sizes, int n_in,
                              void* d_out, int out_size)
{
    const float* inputs = (const float*)d_in[0];
    const float* W_ih   = (const float*)d_in[1];
    const float* W_hh   = (const float*)d_in[2];
    const float* b_ih   = (const float*)d_in[3];
    const float* b_hh   = (const float*)d_in[4];
    const float* aw1    = (const float*)d_in[5];
    const float* ab1    = (const float*)d_in[6];
    const float* aw2    = (const float*)d_in[7];
    const float* ab2    = (const float*)d_in[8];
    const float* hw1    = (const float*)d_in[9];
    const float* hb1    = (const float*)d_in[10];
    const float* hw2    = (const float*)d_in[11];
    const float* hb2    = (const float*)d_in[12];

    float* out = (float*)d_out;
    float* ans_out  = out;                                  // [8, 4096, 512]
    float* halt_out = out + (size_t)OUTER * BATCH * ODIM;   // [8, 4096, 2]

    float *psA, *psB, *pxgbase;
    __half *ps16A, *ps16B, *pxg, *ph1216, *pans16, *pin16;
    __half *pwih, *pwhh, *paw1, *paw2, *phw1;
    cudaGetSymbolAddress((void**)&psA,     g_stateA);
    cudaGetSymbolAddress((void**)&psB,     g_stateB);
    cudaGetSymbolAddress((void**)&pxgbase, g_xgbase);
    cudaGetSymbolAddress((void**)&pxg,     g_xg16);
    cudaGetSymbolAddress((void**)&ph1216,  g_h1216);
    cudaGetSymbolAddress((void**)&ps16A,   g_state16A);
    cudaGetSymbolAddress((void**)&ps16B,   g_state16B);
    cudaGetSymbolAddress((void**)&pans16,  g_ans16);
    cudaGetSymbolAddress((void**)&pin16,   g_in16);
    cudaGetSymbolAddress((void**)&pwih,    g_wih16);
    cudaGetSymbolAddress((void**)&pwhh,    g_whh16);
    cudaGetSymbolAddress((void**)&paw1,    g_aw116);
    cudaGetSymbolAddress((void**)&paw2,    g_aw216);
    cudaGetSymbolAddress((void**)&phw1,    g_hw116);

    const int SMB = 3 * (128 + 128) * 128;  // 98304 (hgemm configs)
    const int SMG = 3 * (128 + 96) * 128;   // 86016 (fused GRU GEMM)
    cudaFuncSetAttribute(hgemm<2, 4, 4, 2, 1, 0, 0, 0>, cudaFuncAttributeMaxDynamicSharedMemorySize, SMB);
    cudaFuncSetAttribute(hgemm<2, 4, 4, 2, 0, 1, 0, 1>, cudaFuncAttributeMaxDynamicSharedMemorySize, SMB);
    cudaFuncSetAttribute(hgemm<2, 4, 4, 2, 0, 1, 1, 0>, cudaFuncAttributeMaxDynamicSharedMemorySize, SMB);
    cudaFuncSetAttribute(hgemm<4, 2, 2, 4, 1, 1, 2, 0>, cudaFuncAttributeMaxDynamicSharedMemorySize, SMB);
    cudaFuncSetAttribute(gru_gemm, cudaFuncAttributeMaxDynamicSharedMemorySize, SMG);

    // 1 launch: convert params + zero state/ans
    init_cvt<<<O7 / 256, 256>>>(inputs, W_ih, W_hh, aw1, aw2, hw1);

    // xg_base = inputs @ W_ih[:, :IDIM]^T + b_ih   (fp32, once)
    hgemm<2, 4, 4, 2, 1, 0, 0, 0><<<dim3((3 * LDIM) / 128, BATCH / 128), 256, SMB>>>(
        pin16, IDIM, IDIM, pin16, IDIM, pwih, pwih, JDIM, 3 * LDIM, b_ih, b_ih,
        nullptr, pxgbase, nullptr, 3 * LDIM, IDIM);

    for (int s = 0; s < OUTER; s++) {
        // xg = xg_base + ans @ W_ih[:, IDIM:]^T     [B, 3L] fp16
        hgemm<2, 4, 4, 2, 0, 1, 0, 1><<<dim3((3 * LDIM) / 128, BATCH / 128), 256, SMB>>>(
            pans16, ODIM, ODIM, pans16, ODIM, pwih + IDIM, pwih + IDIM, JDIM, 3 * LDIM,
            nullptr, nullptr, pxgbase, nullptr, pxg, 3 * LDIM, ODIM);

        // 4x fused GRU GEMM, ping-pong state A->B->A->B->A (ends in A)
        for (int i = 0; i < INNER; i++) {
            const bool even = (i & 1) == 0;
            gru_gemm<<<dim3(LDIM / 32, BATCH / 128), 256, SMG>>>(
                b_hh,
                even ? ps16A : ps16B, even ? psA : psB,
                even ? ps16B : ps16A, even ? psB : psA);
        }

        // h12 = relu(concat(state, ans) @ [aw1; hw1]^T + [ab1; hb1])  [B, 3072] fp16
        hgemm<2, 4, 4, 2, 0, 1, 1, 0><<<dim3(H12 / 128, BATCH / 128), 256, SMB>>>(
            ps16A, LDIM, LDIM, pans16, ODIM, paw1, phw1, JDIM, HDIM, ab1, hb1,
            nullptr, nullptr, ph1216, H12, JDIM);

        // logits -> out (fp32); ans16 = half(tanh(logits))  [reads h1 slice, ld=3072]
        hgemm<4, 2, 2, 4, 1, 1, 2, 0><<<dim3(ODIM / 128, BATCH / 128), 256, SMB>>>(
            ph1216, H12, HDIM, ph1216, H12, paw2, paw2, HDIM, ODIM, ab2, ab2,
            nullptr, ans_out + (size_t)s * BATCH * ODIM, pans16, ODIM, HDIM);

        // halt = h2 @ hw2^T + hb2  (reads h2 slice; runs in logits' tail)
        halt_kernel<<<BATCH / 8, 256>>>(hw2, hb2, halt_out + (size_t)s * BATCH * 2);
    }
}

// round 12
// speedup vs baseline: 1.0135x; 1.0135x over previous
#include <cuda_runtime.h>
#include <cuda_fp16.h>
#include <cstdint>
#include <math.h>

#define BATCH   4096
#define IDIM    1024
#define LDIM    1024
#define HDIM    2048
#define ODIM    512
#define HALTH   1024
#define OUTER   8
#define INNER   4
#define JDIM    (LDIM + ODIM)    // 1536
#define H12     (HDIM + HALTH)   // 3072

// ---------------------------------------------------------------------------
// Device-global scratch (no allocation allowed)
// ---------------------------------------------------------------------------
__device__ float  g_stateA[BATCH * LDIM];
__device__ float  g_stateB[BATCH * LDIM];
__device__ float  g_xgbase[BATCH * 3 * LDIM];

__device__ __half g_xg16[BATCH * 3 * LDIM];
__device__ __half g_h1216[BATCH * H12];      // [h1 (2048) | h2 (1024)] per row

__device__ __half g_state16A[BATCH * LDIM];
__device__ __half g_state16B[BATCH * LDIM];
__device__ __half g_ans16[BATCH * ODIM];
__device__ __half g_in16[BATCH * IDIM];

__device__ __half g_wih16[3 * LDIM * JDIM];
__device__ __half g_whh16[3 * LDIM * LDIM];
__device__ __half g_aw116[HDIM * JDIM];
__device__ __half g_aw216[ODIM * HDIM];
__device__ __half g_hw116[HALTH * JDIM];

__device__ __forceinline__ uint32_t smem_u32(const void* p) {
    uint32_t a;
    asm("{ .reg .u64 t; cvta.to.shared.u64 t, %1; cvt.u32.u64 %0, t; }" : "=r"(a) : "l"(p));
    return a;
}

// Swizzled smem layout: rows of 32 halves (64B) packed into 128B lines.
// Conflict-free for cp.async fill and ldmatrix reads (validated rounds 4-11).
__device__ __forceinline__ uint32_t soff(int r, int c) {
    return (uint32_t)((((r >> 1) * 8) + ((((r & 1) << 2) | c) ^ ((r >> 1) & 7))) << 4);
}

// ---------------------------------------------------------------------------
// Generic fp16 tensor-core GEMM (256 threads, 2 CTAs/SM, BK=32, 4 stages):
//   C = act( concat(A1,A2) @ concatN(W1,W2)^T + biasSel|C0 )
// ---------------------------------------------------------------------------
template <int WM, int WN, int MI, int NG, int W32, int W16, int ACT, int ADDC>
__global__ void __launch_bounds__(WM * WN * 32, 2)
hgemm(const __half* __restrict__ A1, int lda1, int K1,
      const __half* __restrict__ A2, int lda2,
      const __half* __restrict__ W1, const __half* __restrict__ W2,
      int ldw, int nsplit,
      const float* __restrict__ bias1, const float* __restrict__ bias2,
      const float* __restrict__ C0,
      float* __restrict__ C,
      __half* __restrict__ C2,
      int N, int K)
{
    constexpr int THREADS = WM * WN * 32;
    constexpr int BM      = WM * MI * 16;
    constexpr int BN      = WN * NG * 16;
    constexpr int NI      = 2 * NG;
    constexpr int STAGE   = (BM + BN) * 64;
    constexpr int NLOAD   = (BM + BN) * 4 / THREADS;

    extern __shared__ __align__(128) char smem[];
    const uint32_t sb = smem_u32(smem);

    const int tid  = threadIdx.x;
    const int lane = tid & 31;
    const int warp = tid >> 5;
    const int wm   = warp / WN;
    const int wn   = warp % WN;
    const int row0 = blockIdx.y * BM;
    const int col0 = blockIdx.x * BN;

    float c[MI][NI][4];
#pragma unroll
    for (int i = 0; i < MI; i++)
#pragma unroll
        for (int j = 0; j < NI; j++)
#pragma unroll
            for (int k = 0; k < 4; k++) c[i][j][k] = 0.0f;

    const int nc = K >> 5;

    auto load_chunk = [&](int t) {
        const int st = t & 3;
        const int k0 = t << 5;
        const __half* Ab;
        int lda;
        if (k0 < K1) { Ab = A1 + k0;        lda = lda1; }
        else         { Ab = A2 + (k0 - K1); lda = lda2; }
        const uint32_t aB = sb + st * STAGE;
        const uint32_t bB = aB + BM * 64;
#pragma unroll
        for (int j = 0; j < NLOAD; j++) {
            const int idx = j * THREADS + tid;
            if (idx < BM * 4) {
                const int r = idx >> 2, cc = idx & 3;
                const uint32_t d = aB + soff(r, cc);
                const __half* g = Ab + (size_t)(row0 + r) * lda + cc * 8;
                asm volatile("cp.async.cg.shared.global [%0], [%1], 16;" :: "r"(d), "l"(g));
            } else {
                const int li = idx - BM * 4;
                const int r = li >> 2, cc = li & 3;
                const int wr = col0 + r;
                const __half* wbase = (wr < nsplit) ? (W1 + (size_t)wr * ldw)
                                                    : (W2 + (size_t)(wr - nsplit) * ldw);
                const uint32_t d = bB + soff(r, cc);
                asm volatile("cp.async.cg.shared.global [%0], [%1], 16;"
                             :: "r"(d), "l"(wbase + k0 + cc * 8));
            }
        }
        asm volatile("cp.async.commit_group;");
    };

    load_chunk(0);
    load_chunk(1);
    load_chunk(2);

    for (int t = 0; t < nc; t++) {
        if (t + 3 <= nc) asm volatile("cp.async.wait_group 2;");
        else             asm volatile("cp.async.wait_group 0;");
        __syncthreads();
        if (t + 3 < nc) load_chunk(t + 3);

        const uint32_t aB = sb + (t & 3) * STAGE;
        const uint32_t bB = aB + BM * 64;

#pragma unroll
        for (int kh = 0; kh < 2; kh++) {
            uint32_t a[MI][4];
#pragma unroll
            for (int mi = 0; mi < MI; mi++) {
                const int row = wm * (16 * MI) + mi * 16 + (lane & 15);
                const int cc  = kh * 2 + (lane >> 4);
                asm volatile("ldmatrix.sync.aligned.m8n8.x4.shared.b16 {%0,%1,%2,%3}, [%4];"
                             : "=r"(a[mi][0]), "=r"(a[mi][1]), "=r"(a[mi][2]), "=r"(a[mi][3])
                             : "r"(aB + soff(row, cc)));
            }
            uint32_t b[NG][4];
#pragma unroll
            for (int ng = 0; ng < NG; ng++) {
                const int row = wn * (16 * NG) + ng * 16 + (lane & 7) + ((lane >> 4) << 3);
                const int cc  = kh * 2 + ((lane >> 3) & 1);
                asm volatile("ldmatrix.sync.aligned.m8n8.x4.shared.b16 {%0,%1,%2,%3}, [%4];"
                             : "=r"(b[ng][0]), "=r"(b[ng][1]), "=r"(b[ng][2]), "=r"(b[ng][3])
                             : "r"(bB + soff(row, cc)));
            }
#pragma unroll
            for (int mi = 0; mi < MI; mi++)
#pragma unroll
                for (int ng = 0; ng < NG; ng++) {
                    asm volatile(
                        "mma.sync.aligned.m16n8k16.row.col.f32.f16.f16.f32 "
                        "{%0,%1,%2,%3},{%4,%5,%6,%7},{%8,%9},{%0,%1,%2,%3};"
                        : "+f"(c[mi][2 * ng][0]), "+f"(c[mi][2 * ng][1]),
                          "+f"(c[mi][2 * ng][2]), "+f"(c[mi][2 * ng][3])
                        : "r"(a[mi][0]), "r"(a[mi][1]), "r"(a[mi][2]), "r"(a[mi][3]),
                          "r"(b[ng][0]), "r"(b[ng][1]));
                    asm volatile(
                        "mma.sync.aligned.m16n8k16.row.col.f32.f16.f16.f32 "
                        "{%0,%1,%2,%3},{%4,%5,%6,%7},{%8,%9},{%0,%1,%2,%3};"
                        : "+f"(c[mi][2 * ng + 1][0]), "+f"(c[mi][2 * ng + 1][1]),
                          "+f"(c[mi][2 * ng + 1][2]), "+f"(c[mi][2 * ng + 1][3])
                        : "r"(a[mi][0]), "r"(a[mi][1]), "r"(a[mi][2]), "r"(a[mi][3]),
                          "r"(b[ng][2]), "r"(b[ng][3]));
                }
        }
    }

    // Epilogue
#pragma unroll
    for (int mi = 0; mi < MI; mi++) {
        const int r0 = row0 + wm * (16 * MI) + mi * 16 + (lane >> 2);
#pragma unroll
        for (int ni = 0; ni < NI; ni++) {
            const int col = col0 + wn * (16 * NG) + ni * 8 + (lane & 3) * 2;
            const size_t i0 = (size_t)r0 * N + col;
            const size_t i1 = (size_t)(r0 + 8) * N + col;
            float v00, v01, v10, v11;
            if (ADDC) {
                const float2 a0 = *(const float2*)&C0[i0];
                const float2 a1 = *(const float2*)&C0[i1];
                v00 = c[mi][ni][0] + a0.x; v01 = c[mi][ni][1] + a0.y;
                v10 = c[mi][ni][2] + a1.x; v11 = c[mi][ni][3] + a1.y;
            } else {
                const float* bp = (col < nsplit) ? (bias1 + col) : (bias2 + col - nsplit);
                const float b0 = __ldg(bp);
                const float b1 = __ldg(bp + 1);
                v00 = c[mi][ni][0] + b0; v01 = c[mi][ni][1] + b1;
                v10 = c[mi][ni][2] + b0; v11 = c[mi][ni][3] + b1;
            }
            if (ACT == 1) {
                v00 = fmaxf(v00, 0.0f); v01 = fmaxf(v01, 0.0f);
                v10 = fmaxf(v10, 0.0f); v11 = fmaxf(v11, 0.0f);
            }
            if (W32) {
                C[i0] = v00; C[i0 + 1] = v01;
                C[i1] = v10; C[i1 + 1] = v11;
            }
            if (W16) {
                float w00 = v00, w01 = v01, w10 = v10, w11 = v11;
                if (ACT == 2) {
                    w00 = tanhf(v00); w01 = tanhf(v01);
                    w10 = tanhf(v10); w11 = tanhf(v11);
                }
                *(__half2*)&C2[i0] = __floats2half2_rn(w00, w01);
                *(__half2*)&C2[i1] = __floats2half2_rn(w10, w11);
            }
        }
    }
}

// ---------------------------------------------------------------------------
// Fused GRU GEMM, double-buffered state, 256 threads, **3 CTAs/SM**, 4 stages.
// BM=128 (WM=4, MI=2), BN=96 = 3 gates x 32 j's (WN=2, NG=3, warp tile 32x48).
// Gate interleave: B-tile row rb -> weight row gate*L + j; accumulators
// (p, 2+p, 4+p) hold (r,z,n) of the same j.
// ---------------------------------------------------------------------------
__global__ void __launch_bounds__(256, 3)
gru_gemm(const float* __restrict__ bhh,
         const __half* __restrict__ s16in,
         const float* __restrict__ s32in,
         __half* __restrict__ s16out,
         float* __restrict__ s32out)
{
    constexpr int STAGE = (128 + 96) * 64;   // 14336 B

    extern __shared__ __align__(128) char smem[];
    const uint32_t sb = smem_u32(smem);

    const int tid  = threadIdx.x;
    const int lane = tid & 31;
    const int warp = tid >> 5;
    const int wm   = warp >> 1;   // 0..3
    const int wn   = warp & 1;    // 0..1
    const int row0 = blockIdx.y * 128;
    const int c0j  = blockIdx.x * 32;  // 32 j's per CTA

    float c[2][6][4];
#pragma unroll
    for (int i = 0; i < 2; i++)
#pragma unroll
        for (int j = 0; j < 6; j++)
#pragma unroll
            for (int k = 0; k < 4; k++) c[i][j][k] = 0.0f;

    auto load_chunk = [&](int t) {
        const int st = t & 3;
        const int k0 = t << 5;
        const uint32_t aB = sb + st * STAGE;
        const uint32_t bB = aB + 128 * 64;
#pragma unroll
        for (int j = 0; j < 4; j++) {
            const int idx = j * 256 + tid;
            if (idx < 512) {                       // A: 128 rows x 4 chunks
                const int r = idx >> 2, cc = idx & 3;
                const uint32_t d = aB + soff(r, cc);
                const __half* g = s16in + (size_t)(row0 + r) * LDIM + k0 + cc * 8;
                asm volatile("cp.async.cg.shared.global [%0], [%1], 16;" :: "r"(d), "l"(g));
            } else if (idx < 512 + 384) {          // B: 96 rows x 4 chunks
                const int li = idx - 512;
                const int rb = li >> 2, cc = li & 3;
                const int within = rb % 48;
                const int wrow = (within >> 4) * LDIM + c0j + (rb / 48) * 16 + (within & 15);
                const uint32_t d = bB + soff(rb, cc);
                const __half* g = g_whh16 + (size_t)wrow * LDIM + k0 + cc * 8;
                asm volatile("cp.async.cg.shared.global [%0], [%1], 16;" :: "r"(d), "l"(g));
            }
        }
        asm volatile("cp.async.commit_group;");
    };

    load_chunk(0);
    load_chunk(1);
    load_chunk(2);

    const int nc = LDIM >> 5;  // 32
    for (int t = 0; t < nc; t++) {
        if (t + 3 <= nc) asm volatile("cp.async.wait_group 2;");
        else             asm volatile("cp.async.wait_group 0;");
        __syncthreads();
        if (t + 3 < nc) load_chunk(t + 3);

        const uint32_t aB = sb + (t & 3) * STAGE;
        const uint32_t bB = aB + 128 * 64;

#pragma unroll
        for (int kh = 0; kh < 2; kh++) {
            uint32_t a[2][4];
#pragma unroll
            for (int mi = 0; mi < 2; mi++) {
                const int row = wm * 32 + mi * 16 + (lane & 15);
                const int cc  = kh * 2 + (lane >> 4);
                asm volatile("ldmatrix.sync.aligned.m8n8.x4.shared.b16 {%0,%1,%2,%3}, [%4];"
                             : "=r"(a[mi][0]), "=r"(a[mi][1]), "=r"(a[mi][2]), "=r"(a[mi][3])
                             : "r"(aB + soff(row, cc)));
            }
            uint32_t b[3][4];
#pragma unroll
            for (int ng = 0; ng < 3; ng++) {
                const int row = wn * 48 + ng * 16 + (lane & 7) + ((lane >> 4) << 3);
                const int cc  = kh * 2 + ((lane >> 3) & 1);
                asm volatile("ldmatrix.sync.aligned.m8n8.x4.shared.b16 {%0,%1,%2,%3}, [%4];"
                             : "=r"(b[ng][0]), "=r"(b[ng][1]), "=r"(b[ng][2]), "=r"(b[ng][3])
                             : "r"(bB + soff(row, cc)));
            }
#pragma unroll
            for (int mi = 0; mi < 2; mi++)
#pragma unroll
                for (int ng = 0; ng < 3; ng++) {
                    asm volatile(
                        "mma.sync.aligned.m16n8k16.row.col.f32.f16.f16.f32 "
                        "{%0,%1,%2,%3},{%4,%5,%6,%7},{%8,%9},{%0,%1,%2,%3};"
                        : "+f"(c[mi][2 * ng][0]), "+f"(c[mi][2 * ng][1]),
                          "+f"(c[mi][2 * ng][2]), "+f"(c[mi][2 * ng][3])
                        : "r"(a[mi][0]), "r"(a[mi][1]), "r"(a[mi][2]), "r"(a[mi][3]),
                          "r"(b[ng][0]), "r"(b[ng][1]));
                    asm volatile(
                        "mma.sync.aligned.m16n8k16.row.col.f32.f16.f16.f32 "
                        "{%0,%1,%2,%3},{%4,%5,%6,%7},{%8,%9},{%0,%1,%2,%3};"
                        : "+f"(c[mi][2 * ng + 1][0]), "+f"(c[mi][2 * ng + 1][1]),
                          "+f"(c[mi][2 * ng + 1][2]), "+f"(c[mi][2 * ng + 1][3])
                        : "r"(a[mi][0]), "r"(a[mi][1]), "r"(a[mi][2]), "r"(a[mi][3]),
                          "r"(b[ng][2]), "r"(b[ng][3]));
                }
        }
    }

    // Fused GRU epilogue: warp-tile cols = [r 0..15 | z 16..31 | n 32..47]
#pragma unroll
    for (int mi = 0; mi < 2; mi++) {
        const int r0 = row0 + wm * 32 + mi * 16 + (lane >> 2);
#pragma unroll
        for (int p = 0; p < 2; p++) {
            const int j0 = c0j + wn * 16 + p * 8 + (lane & 3) * 2;
            const float2 br = *(const float2*)&bhh[j0];
            const float2 bz = *(const float2*)&bhh[LDIM + j0];
            const float2 bn = *(const float2*)&bhh[2 * LDIM + j0];
            const float* cr = c[mi][p];
            const float* cz = c[mi][2 + p];
            const float* cn = c[mi][4 + p];
#pragma unroll
            for (int h = 0; h < 2; h++) {
                const int row = r0 + h * 8;
                const float hr0 = cr[2 * h] + br.x, hr1 = cr[2 * h + 1] + br.y;
                const float hz0 = cz[2 * h] + bz.x, hz1 = cz[2 * h + 1] + bz.y;
                const float hn0 = cn[2 * h] + bn.x, hn1 = cn[2 * h + 1] + bn.y;
                const size_t xb = (size_t)row * (3 * LDIM) + j0;
                const float2 xr = __half22float2(*(const __half2*)&g_xg16[xb]);
                const float2 xz = __half22float2(*(const __half2*)&g_xg16[xb + LDIM]);
                const float2 xn = __half22float2(*(const __half2*)&g_xg16[xb + 2 * LDIM]);
                const size_t si = (size_t)row * LDIM + j0;
                const float2 s = *(const float2*)&s32in[si];

                const float rr0 = 1.0f / (1.0f + expf(-(xr.x + hr0)));
                const float zz0 = 1.0f / (1.0f + expf(-(xz.x + hz0)));
                const float nn0 = tanhf(xn.x + rr0 * hn0);
                const float rr1 = 1.0f / (1.0f + expf(-(xr.y + hr1)));
                const float zz1 = 1.0f / (1.0f + expf(-(xz.y + hz1)));
                const float nn1 = tanhf(xn.y + rr1 * hn1);

                float2 ns;
                ns.x = (1.0f - zz0) * nn0 + zz0 * s.x;
                ns.y = (1.0f - zz1) * nn1 + zz1 * s.y;
                *(float2*)&s32out[si] = ns;
                *(__half2*)&s16out[si] = __floats2half2_rn(ns.x, ns.y);
            }
        }
    }
}

// ---------------------------------------------------------------------------
// One-shot init: fp16 conversions of all params + zero state/ans buffers.
// ---------------------------------------------------------------------------
#define N_IN   (BATCH * IDIM)
#define N_WIH  (3 * LDIM * JDIM)
#define N_WHH  (3 * LDIM * LDIM)
#define N_AW1  (HDIM * JDIM)
#define N_AW2  (ODIM * HDIM)
#define N_HW1  (HALTH * JDIM)
#define N_ZERO (BATCH * LDIM)
#define O1 N_IN
#define O2 (O1 + N_WIH)
#define O3 (O2 + N_WHH)
#define O4 (O3 + N_AW1)
#define O5 (O4 + N_AW2)
#define O6 (O5 + N_HW1)
#define O7 (O6 + N_ZERO)                 // 22020352 = 86017 * 256

__global__ void init_cvt(const float* __restrict__ inputs,
                         const float* __restrict__ W_ih,
                         const float* __restrict__ W_hh,
                         const float* __restrict__ aw1,
                         const float* __restrict__ aw2,
                         const float* __restrict__ hw1)
{
    const int i = blockIdx.x * blockDim.x + threadIdx.x;
    if (i < O1)      g_in16[i]         = __float2half_rn(inputs[i]);
    else if (i < O2) g_wih16[i - O1]   = __float2half_rn(W_ih[i - O1]);
    else if (i < O3) g_whh16[i - O2]   = __float2half_rn(W_hh[i - O2]);
    else if (i < O4) g_aw116[i - O3]   = __float2half_rn(aw1[i - O3]);
    else if (i < O5) g_aw216[i - O4]   = __float2half_rn(aw2[i - O4]);
    else if (i < O6) g_hw116[i - O5]   = __float2half_rn(hw1[i - O5]);
    else {
        const int j = i - O6;
        g_stateA[j]   = 0.0f;
        g_state16A[j] = __ushort_as_half((unsigned short)0);
        if (j < BATCH * ODIM) g_ans16[j] = __ushort_as_half((unsigned short)0);
    }
}

// ---------------------------------------------------------------------------
// Halt head: reads h2 slice of the merged h12 buffer.
// ---------------------------------------------------------------------------
__global__ void halt_kernel(const float* __restrict__ hw2,
                            const float* __restrict__ hb2,
                            float* __restrict__ out)
{
    const int row  = blockIdx.x * (blockDim.x >> 5) + (threadIdx.x >> 5);
    const int lane = threadIdx.x & 31;
    const __half2* h = (const __half2*)(g_h1216 + (size_t)row * H12 + HDIM);
    const float2* w0 = (const float2*)hw2;
    const float2* w1 = (const float2*)(hw2 + HALTH);
    float s0 = 0.0f, s1 = 0.0f;
    for (int k = lane; k < HALTH / 2; k += 32) {
        const float2 v  = __half22float2(h[k]);
        const float2 a0 = w0[k];
        const float2 a1 = w1[k];
        s0 += v.x * a0.x + v.y * a0.y;
        s1 += v.x * a1.x + v.y * a1.y;
    }
#pragma unroll
    for (int o = 16; o > 0; o >>= 1) {
        s0 += __shfl_down_sync(0xFFFFFFFFu, s0, o);
        s1 += __shfl_down_sync(0xFFFFFFFFu, s1, o);
    }
    if (lane == 0) {
        out[(size_t)row * 2]     = s0 + hb2[0];
        out[(size_t)row * 2 + 1] = s1 + hb2[1];
    }
}

// ---------------------------------------------------------------------------
// Host orchestration
// ---------------------------------------------------------------------------
extern "C" void kernel_launch(void* const* d_in, const int* in_sizes, int n_in,
                              void* d_out, int out_size)
{
    const float* inputs = (const float*)d_in[0];
    const float* W_ih   = (const float*)d_in[1];
    const float* W_hh   = (const float*)d_in[2];
    const float* b_ih   = (const float*)d_in[3];
    const float* b_hh   = (const float*)d_in[4];
    const float* aw1    = (const float*)d_in[5];
    const float* ab1    = (const float*)d_in[6];
    const float* aw2    = (const float*)d_in[7];
    const float* ab2    = (const float*)d_in[8];
    const float* hw1    = (const float*)d_in[9];
    const float* hb1    = (const float*)d_in[10];
    const float* hw2    = (const float*)d_in[11];
    const float* hb2    = (const float*)d_in[12];

    float* out = (float*)d_out;
    float* ans_out  = out;                                  // [8, 4096, 512]
    float* halt_out = out + (size_t)OUTER * BATCH * ODIM;   // [8, 4096, 2]

    float *psA, *psB, *pxgbase;
    __half *ps16A, *ps16B, *pxg, *ph1216, *pans16, *pin16;
    __half *pwih, *pwhh, *paw1, *paw2, *phw1;
    cudaGetSymbolAddress((void**)&psA,     g_stateA);
    cudaGetSymbolAddress((void**)&psB,     g_stateB);
    cudaGetSymbolAddress((void**)&pxgbase, g_xgbase);
    cudaGetSymbolAddress((void**)&pxg,     g_xg16);
    cudaGetSymbolAddress((void**)&ph1216,  g_h1216);
    cudaGetSymbolAddress((void**)&ps16A,   g_state16A);
    cudaGetSymbolAddress((void**)&ps16B,   g_state16B);
    cudaGetSymbolAddress((void**)&pans16,  g_ans16);
    cudaGetSymbolAddress((void**)&pin16,   g_in16);
    cudaGetSymbolAddress((void**)&pwih,    g_wih16);
    cudaGetSymbolAddress((void**)&pwhh,    g_whh16);
    cudaGetSymbolAddress((void**)&paw1,    g_aw116);
    cudaGetSymbolAddress((void**)&paw2,    g_aw216);
    cudaGetSymbolAddress((void**)&phw1,    g_hw116);

    const int SMB = 4 * (128 + 128) * 64;  // 65536 (hgemm configs)
    const int SMG = 4 * (128 + 96) * 64;   // 57344 (fused GRU GEMM)
    cudaFuncSetAttribute(hgemm<2, 4, 4, 2, 1, 0, 0, 0>, cudaFuncAttributeMaxDynamicSharedMemorySize, SMB);
    cudaFuncSetAttribute(hgemm<2, 4, 4, 2, 0, 1, 0, 1>, cudaFuncAttributeMaxDynamicSharedMemorySize, SMB);
    cudaFuncSetAttribute(hgemm<2, 4, 4, 2, 0, 1, 1, 0>, cudaFuncAttributeMaxDynamicSharedMemorySize, SMB);
    cudaFuncSetAttribute(hgemm<4, 2, 2, 4, 1, 1, 2, 0>, cudaFuncAttributeMaxDynamicSharedMemorySize, SMB);
    cudaFuncSetAttribute(gru_gemm, cudaFuncAttributeMaxDynamicSharedMemorySize, SMG);

    // 1 launch: convert params + zero state/ans
    init_cvt<<<O7 / 256, 256>>>(inputs, W_ih, W_hh, aw1, aw2, hw1);

    // xg_base = inputs @ W_ih[:, :IDIM]^T + b_ih   (fp32, once)
    hgemm<2, 4, 4, 2, 1, 0, 0, 0><<<dim3((3 * LDIM) / 128, BATCH / 128), 256, SMB>>>(
        pin16, IDIM, IDIM, pin16, IDIM, pwih, pwih, JDIM, 3 * LDIM, b_ih, b_ih,
        nullptr, pxgbase, nullptr, 3 * LDIM, IDIM);

    for (int s = 0; s < OUTER; s++) {
        // xg = xg_base + ans @ W_ih[:, IDIM:]^T     [B, 3L] fp16
        hgemm<2, 4, 4, 2, 0, 1, 0, 1><<<dim3((3 * LDIM) / 128, BATCH / 128), 256, SMB>>>(
            pans16, ODIM, ODIM, pans16, ODIM, pwih + IDIM, pwih + IDIM, JDIM, 3 * LDIM,
            nullptr, nullptr, pxgbase, nullptr, pxg, 3 * LDIM, ODIM);

        // 4x fused GRU GEMM, ping-pong state A->B->A->B->A (ends in A)
        for (int i = 0; i < INNER; i++) {
            const bool even = (i & 1) == 0;
            gru_gemm<<<dim3(LDIM / 32, BATCH / 128), 256, SMG>>>(
                b_hh,
                even ? ps16A : ps16B, even ? psA : psB,
                even ? ps16B : ps16A, even ? psB : psA);
        }

        // h12 = relu(concat(state, ans) @ [aw1; hw1]^T + [ab1; hb1])  [B, 3072] fp16
        hgemm<2, 4, 4, 2, 0, 1, 1, 0><<<dim3(H12 / 128, BATCH / 128), 256, SMB>>>(
            ps16A, LDIM, LDIM, pans16, ODIM, paw1, phw1, JDIM, HDIM, ab1, hb1,
            nullptr, nullptr, ph1216, H12, JDIM);

        // logits -> out (fp32); ans16 = half(tanh(logits))  [reads h1 slice, ld=3072]
        hgemm<4, 2, 2, 4, 1, 1, 2, 0><<<dim3(ODIM / 128, BATCH / 128), 256, SMB>>>(
            ph1216, H12, HDIM, ph1216, H12, paw2, paw2, HDIM, ODIM, ab2, ab2,
            nullptr, ans_out + (size_t)s * BATCH * ODIM, pans16, ODIM, HDIM);

        // halt = h2 @ hw2^T + hb2  (reads h2 slice; runs in logits' tail)
        halt_kernel<<<BATCH / 8, 256>>>(hw2, hb2, halt_out + (size_t)s * BATCH * 2);
    }
}

// round 13
// speedup vs baseline: 1.1858x; 1.1700x over previous
#include <cuda_runtime.h>
#include <cuda_fp16.h>
#include <cstdint>
#include <math.h>

#define BATCH   4096
#define IDIM    1024
#define LDIM    1024
#define HDIM    2048
#define ODIM    512
#define HALTH   1024
#define OUTER   8
#define INNER   4
#define JDIM    (LDIM + ODIM)    // 1536
#define H12     (HDIM + HALTH)   // 3072
#define HB      (BATCH / 2)      // rows per stream half

// ---------------------------------------------------------------------------
// Device-global scratch (no allocation allowed)
// ---------------------------------------------------------------------------
__device__ float  g_stateA[BATCH * LDIM];
__device__ float  g_stateB[BATCH * LDIM];
__device__ float  g_xgbase[BATCH * 3 * LDIM];

__device__ __half g_xg16[BATCH * 3 * LDIM];
__device__ __half g_h1216[BATCH * H12];      // [h1 (2048) | h2 (1024)] per row

__device__ __half g_state16A[BATCH * LDIM];
__device__ __half g_state16B[BATCH * LDIM];
__device__ __half g_ans16[BATCH * ODIM];
__device__ __half g_in16[BATCH * IDIM];

__device__ __half g_wih16[3 * LDIM * JDIM];
__device__ __half g_whh16[3 * LDIM * LDIM];
__device__ __half g_aw116[HDIM * JDIM];
__device__ __half g_aw216[ODIM * HDIM];
__device__ __half g_hw116[HALTH * JDIM];

__device__ __forceinline__ uint32_t smem_u32(const void* p) {
    uint32_t a;
    asm("{ .reg .u64 t; cvta.to.shared.u64 t, %1; cvt.u32.u64 %0, t; }" : "=r"(a) : "l"(p));
    return a;
}

// Swizzled smem layout: rows of 32 halves (64B) packed into 128B lines.
// Conflict-free for cp.async fill and ldmatrix reads (validated rounds 4-12).
__device__ __forceinline__ uint32_t soff(int r, int c) {
    return (uint32_t)((((r >> 1) * 8) + ((((r & 1) << 2) | c) ^ ((r >> 1) & 7))) << 4);
}

// ---------------------------------------------------------------------------
// Generic fp16 tensor-core GEMM (256 threads, 2 CTAs/SM, BK=32, 4 stages):
//   C = act( concat(A1,A2) @ concatN(W1,W2)^T + biasSel|C0 )
// ---------------------------------------------------------------------------
template <int WM, int WN, int MI, int NG, int W32, int W16, int ACT, int ADDC>
__global__ void __launch_bounds__(WM * WN * 32, 2)
hgemm(const __half* __restrict__ A1, int lda1, int K1,
      const __half* __restrict__ A2, int lda2,
      const __half* __restrict__ W1, const __half* __restrict__ W2,
      int ldw, int nsplit,
      const float* __restrict__ bias1, const float* __restrict__ bias2,
      const float* __restrict__ C0,
      float* __restrict__ C,
      __half* __restrict__ C2,
      int N, int K)
{
    constexpr int THREADS = WM * WN * 32;
    constexpr int BM      = WM * MI * 16;
    constexpr int BN      = WN * NG * 16;
    constexpr int NI      = 2 * NG;
    constexpr int STAGE   = (BM + BN) * 64;
    constexpr int NLOAD   = (BM + BN) * 4 / THREADS;

    extern __shared__ __align__(128) char smem[];
    const uint32_t sb = smem_u32(smem);

    const int tid  = threadIdx.x;
    const int lane = tid & 31;
    const int warp = tid >> 5;
    const int wm   = warp / WN;
    const int wn   = warp % WN;
    const int row0 = blockIdx.y * BM;
    const int col0 = blockIdx.x * BN;

    float c[MI][NI][4];
#pragma unroll
    for (int i = 0; i < MI; i++)
#pragma unroll
        for (int j = 0; j < NI; j++)
#pragma unroll
            for (int k = 0; k < 4; k++) c[i][j][k] = 0.0f;

    const int nc = K >> 5;

    auto load_chunk = [&](int t) {
        const int st = t & 3;
        const int k0 = t << 5;
        const __half* Ab;
        int lda;
        if (k0 < K1) { Ab = A1 + k0;        lda = lda1; }
        else         { Ab = A2 + (k0 - K1); lda = lda2; }
        const uint32_t aB = sb + st * STAGE;
        const uint32_t bB = aB + BM * 64;
#pragma unroll
        for (int j = 0; j < NLOAD; j++) {
            const int idx = j * THREADS + tid;
            if (idx < BM * 4) {
                const int r = idx >> 2, cc = idx & 3;
                const uint32_t d = aB + soff(r, cc);
                const __half* g = Ab + (size_t)(row0 + r) * lda + cc * 8;
                asm volatile("cp.async.cg.shared.global [%0], [%1], 16;" :: "r"(d), "l"(g));
            } else {
                const int li = idx - BM * 4;
                const int r = li >> 2, cc = li & 3;
                const int wr = col0 + r;
                const __half* wbase = (wr < nsplit) ? (W1 + (size_t)wr * ldw)
                                                    : (W2 + (size_t)(wr - nsplit) * ldw);
                const uint32_t d = bB + soff(r, cc);
                asm volatile("cp.async.cg.shared.global [%0], [%1], 16;"
                             :: "r"(d), "l"(wbase + k0 + cc * 8));
            }
        }
        asm volatile("cp.async.commit_group;");
    };

    load_chunk(0);
    load_chunk(1);
    load_chunk(2);

    for (int t = 0; t < nc; t++) {
        if (t + 3 <= nc) asm volatile("cp.async.wait_group 2;");
        else             asm volatile("cp.async.wait_group 0;");
        __syncthreads();
        if (t + 3 < nc) load_chunk(t + 3);

        const uint32_t aB = sb + (t & 3) * STAGE;
        const uint32_t bB = aB + BM * 64;

#pragma unroll
        for (int kh = 0; kh < 2; kh++) {
            uint32_t a[MI][4];
#pragma unroll
            for (int mi = 0; mi < MI; mi++) {
                const int row = wm * (16 * MI) + mi * 16 + (lane & 15);
                const int cc  = kh * 2 + (lane >> 4);
                asm volatile("ldmatrix.sync.aligned.m8n8.x4.shared.b16 {%0,%1,%2,%3}, [%4];"
                             : "=r"(a[mi][0]), "=r"(a[mi][1]), "=r"(a[mi][2]), "=r"(a[mi][3])
                             : "r"(aB + soff(row, cc)));
            }
            uint32_t b[NG][4];
#pragma unroll
            for (int ng = 0; ng < NG; ng++) {
                const int row = wn * (16 * NG) + ng * 16 + (lane & 7) + ((lane >> 4) << 3);
                const int cc  = kh * 2 + ((lane >> 3) & 1);
                asm volatile("ldmatrix.sync.aligned.m8n8.x4.shared.b16 {%0,%1,%2,%3}, [%4];"
                             : "=r"(b[ng][0]), "=r"(b[ng][1]), "=r"(b[ng][2]), "=r"(b[ng][3])
                             : "r"(bB + soff(row, cc)));
            }
#pragma unroll
            for (int mi = 0; mi < MI; mi++)
#pragma unroll
                for (int ng = 0; ng < NG; ng++) {
                    asm volatile(
                        "mma.sync.aligned.m16n8k16.row.col.f32.f16.f16.f32 "
                        "{%0,%1,%2,%3},{%4,%5,%6,%7},{%8,%9},{%0,%1,%2,%3};"
                        : "+f"(c[mi][2 * ng][0]), "+f"(c[mi][2 * ng][1]),
                          "+f"(c[mi][2 * ng][2]), "+f"(c[mi][2 * ng][3])
                        : "r"(a[mi][0]), "r"(a[mi][1]), "r"(a[mi][2]), "r"(a[mi][3]),
                          "r"(b[ng][0]), "r"(b[ng][1]));
                    asm volatile(
                        "mma.sync.aligned.m16n8k16.row.col.f32.f16.f16.f32 "
                        "{%0,%1,%2,%3},{%4,%5,%6,%7},{%8,%9},{%0,%1,%2,%3};"
                        : "+f"(c[mi][2 * ng + 1][0]), "+f"(c[mi][2 * ng + 1][1]),
                          "+f"(c[mi][2 * ng + 1][2]), "+f"(c[mi][2 * ng + 1][3])
                        : "r"(a[mi][0]), "r"(a[mi][1]), "r"(a[mi][2]), "r"(a[mi][3]),
                          "r"(b[ng][2]), "r"(b[ng][3]));
                }
        }
    }

    // Epilogue
#pragma unroll
    for (int mi = 0; mi < MI; mi++) {
        const int r0 = row0 + wm * (16 * MI) + mi * 16 + (lane >> 2);
#pragma unroll
        for (int ni = 0; ni < NI; ni++) {
            const int col = col0 + wn * (16 * NG) + ni * 8 + (lane & 3) * 2;
            const size_t i0 = (size_t)r0 * N + col;
            const size_t i1 = (size_t)(r0 + 8) * N + col;
            float v00, v01, v10, v11;
            if (ADDC) {
                const float2 a0 = *(const float2*)&C0[i0];
                const float2 a1 = *(const float2*)&C0[i1];
                v00 = c[mi][ni][0] + a0.x; v01 = c[mi][ni][1] + a0.y;
                v10 = c[mi][ni][2] + a1.x; v11 = c[mi][ni][3] + a1.y;
            } else {
                const float* bp = (col < nsplit) ? (bias1 + col) : (bias2 + col - nsplit);
                const float b0 = __ldg(bp);
                const float b1 = __ldg(bp + 1);
                v00 = c[mi][ni][0] + b0; v01 = c[mi][ni][1] + b1;
                v10 = c[mi][ni][2] + b0; v11 = c[mi][ni][3] + b1;
            }
            if (ACT == 1) {
                v00 = fmaxf(v00, 0.0f); v01 = fmaxf(v01, 0.0f);
                v10 = fmaxf(v10, 0.0f); v11 = fmaxf(v11, 0.0f);
            }
            if (W32) {
                C[i0] = v00; C[i0 + 1] = v01;
                C[i1] = v10; C[i1 + 1] = v11;
            }
            if (W16) {
                float w00 = v00, w01 = v01, w10 = v10, w11 = v11;
                if (ACT == 2) {
                    w00 = tanhf(v00); w01 = tanhf(v01);
                    w10 = tanhf(v10); w11 = tanhf(v11);
                }
                *(__half2*)&C2[i0] = __floats2half2_rn(w00, w01);
                *(__half2*)&C2[i1] = __floats2half2_rn(w10, w11);
            }
        }
    }
}

// ---------------------------------------------------------------------------
// Fused GRU GEMM, double-buffered state, 256 threads, 2 CTAs/SM, 4 stages
// (exact round-10 shape). BM=128 (WM=4, MI=2), BN=96 (WN=2, NG=3).
// Gate interleave: B-tile row rb -> weight row gate*L + j; accumulators
// (p, 2+p, 4+p) hold (r,z,n) of the same j. xg passed as pointer (row-offset).
// ---------------------------------------------------------------------------
__global__ void __launch_bounds__(256, 2)
gru_gemm(const float* __restrict__ bhh,
         const __half* __restrict__ xg,
         const __half* __restrict__ s16in,
         const float* __restrict__ s32in,
         __half* __restrict__ s16out,
         float* __restrict__ s32out)
{
    constexpr int STAGE = (128 + 96) * 64;   // 14336 B

    extern __shared__ __align__(128) char smem[];
    const uint32_t sb = smem_u32(smem);

    const int tid  = threadIdx.x;
    const int lane = tid & 31;
    const int warp = tid >> 5;
    const int wm   = warp >> 1;   // 0..3
    const int wn   = warp & 1;    // 0..1
    const int row0 = blockIdx.y * 128;
    const int c0j  = blockIdx.x * 32;  // 32 j's per CTA

    float c[2][6][4];
#pragma unroll
    for (int i = 0; i < 2; i++)
#pragma unroll
        for (int j = 0; j < 6; j++)
#pragma unroll
            for (int k = 0; k < 4; k++) c[i][j][k] = 0.0f;

    auto load_chunk = [&](int t) {
        const int st = t & 3;
        const int k0 = t << 5;
        const uint32_t aB = sb + st * STAGE;
        const uint32_t bB = aB + 128 * 64;
#pragma unroll
        for (int j = 0; j < 4; j++) {
            const int idx = j * 256 + tid;
            if (idx < 512) {                       // A: 128 rows x 4 chunks
                const int r = idx >> 2, cc = idx & 3;
                const uint32_t d = aB + soff(r, cc);
                const __half* g = s16in + (size_t)(row0 + r) * LDIM + k0 + cc * 8;
                asm volatile("cp.async.cg.shared.global [%0], [%1], 16;" :: "r"(d), "l"(g));
            } else if (idx < 512 + 384) {          // B: 96 rows x 4 chunks
                const int li = idx - 512;
                const int rb = li >> 2, cc = li & 3;
                const int within = rb % 48;
                const int wrow = (within >> 4) * LDIM + c0j + (rb / 48) * 16 + (within & 15);
                const uint32_t d = bB + soff(rb, cc);
                const __half* g = g_whh16 + (size_t)wrow * LDIM + k0 + cc * 8;
                asm volatile("cp.async.cg.shared.global [%0], [%1], 16;" :: "r"(d), "l"(g));
            }
        }
        asm volatile("cp.async.commit_group;");
    };

    load_chunk(0);
    load_chunk(1);
    load_chunk(2);

    const int nc = LDIM >> 5;  // 32
    for (int t = 0; t < nc; t++) {
        if (t + 3 <= nc) asm volatile("cp.async.wait_group 2;");
        else             asm volatile("cp.async.wait_group 0;");
        __syncthreads();
        if (t + 3 < nc) load_chunk(t + 3);

        const uint32_t aB = sb + (t & 3) * STAGE;
        const uint32_t bB = aB + 128 * 64;

#pragma unroll
        for (int kh = 0; kh < 2; kh++) {
            uint32_t a[2][4];
#pragma unroll
            for (int mi = 0; mi < 2; mi++) {
                const int row = wm * 32 + mi * 16 + (lane & 15);
                const int cc  = kh * 2 + (lane >> 4);
                asm volatile("ldmatrix.sync.aligned.m8n8.x4.shared.b16 {%0,%1,%2,%3}, [%4];"
                             : "=r"(a[mi][0]), "=r"(a[mi][1]), "=r"(a[mi][2]), "=r"(a[mi][3])
                             : "r"(aB + soff(row, cc)));
            }
            uint32_t b[3][4];
#pragma unroll
            for (int ng = 0; ng < 3; ng++) {
                const int row = wn * 48 + ng * 16 + (lane & 7) + ((lane >> 4) << 3);
                const int cc  = kh * 2 + ((lane >> 3) & 1);
                asm volatile("ldmatrix.sync.aligned.m8n8.x4.shared.b16 {%0,%1,%2,%3}, [%4];"
                             : "=r"(b[ng][0]), "=r"(b[ng][1]), "=r"(b[ng][2]), "=r"(b[ng][3])
                             : "r"(bB + soff(row, cc)));
            }
#pragma unroll
            for (int mi = 0; mi < 2; mi++)
#pragma unroll
                for (int ng = 0; ng < 3; ng++) {
                    asm volatile(
                        "mma.sync.aligned.m16n8k16.row.col.f32.f16.f16.f32 "
                        "{%0,%1,%2,%3},{%4,%5,%6,%7},{%8,%9},{%0,%1,%2,%3};"
                        : "+f"(c[mi][2 * ng][0]), "+f"(c[mi][2 * ng][1]),
                          "+f"(c[mi][2 * ng][2]), "+f"(c[mi][2 * ng][3])
                        : "r"(a[mi][0]), "r"(a[mi][1]), "r"(a[mi][2]), "r"(a[mi][3]),
                          "r"(b[ng][0]), "r"(b[ng][1]));
                    asm volatile(
                        "mma.sync.aligned.m16n8k16.row.col.f32.f16.f16.f32 "
                        "{%0,%1,%2,%3},{%4,%5,%6,%7},{%8,%9},{%0,%1,%2,%3};"
                        : "+f"(c[mi][2 * ng + 1][0]), "+f"(c[mi][2 * ng + 1][1]),
                          "+f"(c[mi][2 * ng + 1][2]), "+f"(c[mi][2 * ng + 1][3])
                        : "r"(a[mi][0]), "r"(a[mi][1]), "r"(a[mi][2]), "r"(a[mi][3]),
                          "r"(b[ng][2]), "r"(b[ng][3]));
                }
        }
    }

    // Fused GRU epilogue: warp-tile cols = [r 0..15 | z 16..31 | n 32..47]
#pragma unroll
    for (int mi = 0; mi < 2; mi++) {
        const int r0 = row0 + wm * 32 + mi * 16 + (lane >> 2);
#pragma unroll
        for (int p = 0; p < 2; p++) {
            const int j0 = c0j + wn * 16 + p * 8 + (lane & 3) * 2;
            const float2 br = *(const float2*)&bhh[j0];
            const float2 bz = *(const float2*)&bhh[LDIM + j0];
            const float2 bn = *(const float2*)&bhh[2 * LDIM + j0];
            const float* cr = c[mi][p];
            const float* cz = c[mi][2 + p];
            const float* cn = c[mi][4 + p];
#pragma unroll
            for (int h = 0; h < 2; h++) {
                const int row = r0 + h * 8;
                const float hr0 = cr[2 * h] + br.x, hr1 = cr[2 * h + 1] + br.y;
                const float hz0 = cz[2 * h] + bz.x, hz1 = cz[2 * h + 1] + bz.y;
                const float hn0 = cn[2 * h] + bn.x, hn1 = cn[2 * h + 1] + bn.y;
                const size_t xb = (size_t)row * (3 * LDIM) + j0;
                const float2 xr = __half22float2(*(const __half2*)&xg[xb]);
                const float2 xz = __half22float2(*(const __half2*)&xg[xb + LDIM]);
                const float2 xn = __half22float2(*(const __half2*)&xg[xb + 2 * LDIM]);
                const size_t si = (size_t)row * LDIM + j0;
                const float2 s = *(const float2*)&s32in[si];

                const float rr0 = 1.0f / (1.0f + expf(-(xr.x + hr0)));
                const float zz0 = 1.0f / (1.0f + expf(-(xz.x + hz0)));
                const float nn0 = tanhf(xn.x + rr0 * hn0);
                const float rr1 = 1.0f / (1.0f + expf(-(xr.y + hr1)));
                const float zz1 = 1.0f / (1.0f + expf(-(xz.y + hz1)));
                const float nn1 = tanhf(xn.y + rr1 * hn1);

                float2 ns;
                ns.x = (1.0f - zz0) * nn0 + zz0 * s.x;
                ns.y = (1.0f - zz1) * nn1 + zz1 * s.y;
                *(float2*)&s32out[si] = ns;
                *(__half2*)&s16out[si] = __floats2half2_rn(ns.x, ns.y);
            }
        }
    }
}

// ---------------------------------------------------------------------------
// One-shot init: fp16 conversions of all params + zero state/ans buffers.
// ---------------------------------------------------------------------------
#define N_IN   (BATCH * IDIM)
#define N_WIH  (3 * LDIM * JDIM)
#define N_WHH  (3 * LDIM * LDIM)
#define N_AW1  (HDIM * JDIM)
#define N_AW2  (ODIM * HDIM)
#define N_HW1  (HALTH * JDIM)
#define N_ZERO (BATCH * LDIM)
#define O1 N_IN
#define O2 (O1 + N_WIH)
#define O3 (O2 + N_WHH)
#define O4 (O3 + N_AW1)
#define O5 (O4 + N_AW2)
#define O6 (O5 + N_HW1)
#define O7 (O6 + N_ZERO)                 // 22020352 = 86017 * 256

__global__ void init_cvt(const float* __restrict__ inputs,
                         const float* __restrict__ W_ih,
                         const float* __restrict__ W_hh,
                         const float* __restrict__ aw1,
                         const float* __restrict__ aw2,
                         const float* __restrict__ hw1)
{
    const int i = blockIdx.x * blockDim.x + threadIdx.x;
    if (i < O1)      g_in16[i]         = __float2half_rn(inputs[i]);
    else if (i < O2) g_wih16[i - O1]   = __float2half_rn(W_ih[i - O1]);
    else if (i < O3) g_whh16[i - O2]   = __float2half_rn(W_hh[i - O2]);
    else if (i < O4) g_aw116[i - O3]   = __float2half_rn(aw1[i - O3]);
    else if (i < O5) g_aw216[i - O4]   = __float2half_rn(aw2[i - O4]);
    else if (i < O6) g_hw116[i - O5]   = __float2half_rn(hw1[i - O5]);
    else {
        const int j = i - O6;
        g_stateA[j]   = 0.0f;
        g_state16A[j] = __ushort_as_half((unsigned short)0);
        if (j < BATCH * ODIM) g_ans16[j] = __ushort_as_half((unsigned short)0);
    }
}

// ---------------------------------------------------------------------------
// Halt head: reads h2 slice of the merged h12 buffer (pointer passed in).
// ---------------------------------------------------------------------------
__global__ void halt_kernel(const __half* __restrict__ h12,
                            const float* __restrict__ hw2,
                            const float* __restrict__ hb2,
                            float* __restrict__ out)
{
    const int row  = blockIdx.x * (blockDim.x >> 5) + (threadIdx.x >> 5);
    const int lane = threadIdx.x & 31;
    const __half2* h = (const __half2*)(h12 + (size_t)row * H12 + HDIM);
    const float2* w0 = (const float2*)hw2;
    const float2* w1 = (const float2*)(hw2 + HALTH);
    float s0 = 0.0f, s1 = 0.0f;
    for (int k = lane; k < HALTH / 2; k += 32) {
        const float2 v  = __half22float2(h[k]);
        const float2 a0 = w0[k];
        const float2 a1 = w1[k];
        s0 += v.x * a0.x + v.y * a0.y;
        s1 += v.x * a1.x + v.y * a1.y;
    }
#pragma unroll
    for (int o = 16; o > 0; o >>= 1) {
        s0 += __shfl_down_sync(0xFFFFFFFFu, s0, o);
        s1 += __shfl_down_sync(0xFFFFFFFFu, s1, o);
    }
    if (lane == 0) {
        out[(size_t)row * 2]     = s0 + hb2[0];
        out[(size_t)row * 2 + 1] = s1 + hb2[1];
    }
}

// ---------------------------------------------------------------------------
// Host orchestration: 2-stream fork over independent batch halves.
// ---------------------------------------------------------------------------
extern "C" void kernel_launch(void* const* d_in, const int* in_sizes, int n_in,
                              void* d_out, int out_size)
{
    const float* inputs = (const float*)d_in[0];
    const float* W_ih   = (const float*)d_in[1];
    const float* W_hh   = (const float*)d_in[2];
    const float* b_ih   = (const float*)d_in[3];
    const float* b_hh   = (const float*)d_in[4];
    const float* aw1    = (const float*)d_in[5];
    const float* ab1    = (const float*)d_in[6];
    const float* aw2    = (const float*)d_in[7];
    const float* ab2    = (const float*)d_in[8];
    const float* hw1    = (const float*)d_in[9];
    const float* hb1    = (const float*)d_in[10];
    const float* hw2    = (const float*)d_in[11];
    const float* hb2    = (const float*)d_in[12];

    float* out = (float*)d_out;
    float* ans_out  = out;                                  // [8, 4096, 512]
    float* halt_out = out + (size_t)OUTER * BATCH * ODIM;   // [8, 4096, 2]

    float *psA, *psB, *pxgbase;
    __half *ps16A, *ps16B, *pxg, *ph1216, *pans16, *pin16;
    __half *pwih, *pwhh, *paw1, *paw2, *phw1;
    cudaGetSymbolAddress((void**)&psA,     g_stateA);
    cudaGetSymbolAddress((void**)&psB,     g_stateB);
    cudaGetSymbolAddress((void**)&pxgbase, g_xgbase);
    cudaGetSymbolAddress((void**)&pxg,     g_xg16);
    cudaGetSymbolAddress((void**)&ph1216,  g_h1216);
    cudaGetSymbolAddress((void**)&ps16A,   g_state16A);
    cudaGetSymbolAddress((void**)&ps16B,   g_state16B);
    cudaGetSymbolAddress((void**)&pans16,  g_ans16);
    cudaGetSymbolAddress((void**)&pin16,   g_in16);
    cudaGetSymbolAddress((void**)&pwih,    g_wih16);
    cudaGetSymbolAddress((void**)&pwhh,    g_whh16);
    cudaGetSymbolAddress((void**)&paw1,    g_aw116);
    cudaGetSymbolAddress((void**)&paw2,    g_aw216);
    cudaGetSymbolAddress((void**)&phw1,    g_hw116);

    const int SMB = 4 * (128 + 128) * 64;  // 65536 (hgemm configs)
    const int SMG = 4 * (128 + 96) * 64;   // 57344 (fused GRU GEMM)
    cudaFuncSetAttribute(hgemm<2, 4, 4, 2, 1, 0, 0, 0>, cudaFuncAttributeMaxDynamicSharedMemorySize, SMB);
    cudaFuncSetAttribute(hgemm<2, 4, 4, 2, 0, 1, 0, 1>, cudaFuncAttributeMaxDynamicSharedMemorySize, SMB);
    cudaFuncSetAttribute(hgemm<2, 4, 4, 2, 0, 1, 1, 0>, cudaFuncAttributeMaxDynamicSharedMemorySize, SMB);
    cudaFuncSetAttribute(hgemm<4, 2, 2, 4, 1, 1, 2, 0>, cudaFuncAttributeMaxDynamicSharedMemorySize, SMB);
    cudaFuncSetAttribute(gru_gemm, cudaFuncAttributeMaxDynamicSharedMemorySize, SMG);

    // One-time stream/event setup (first call is the uncaptured correctness run;
    // captured calls reuse the same handles -> identical graph every capture).
    static cudaStream_t s2 = nullptr;
    static cudaEvent_t  evF = nullptr, evJ = nullptr;
    if (s2 == nullptr) {
        cudaStreamCreateWithFlags(&s2, cudaStreamNonBlocking);
        cudaEventCreateWithFlags(&evF, cudaEventDisableTiming);
        cudaEventCreateWithFlags(&evJ, cudaEventDisableTiming);
    }

    // ---- Prologue on main (capture-origin) stream ----
    init_cvt<<<O7 / 256, 256>>>(inputs, W_ih, W_hh, aw1, aw2, hw1);

    // xg_base = inputs @ W_ih[:, :IDIM]^T + b_ih   (fp32, full batch, once)
    hgemm<2, 4, 4, 2, 1, 0, 0, 0><<<dim3((3 * LDIM) / 128, BATCH / 128), 256, SMB>>>(
        pin16, IDIM, IDIM, pin16, IDIM, pwih, pwih, JDIM, 3 * LDIM, b_ih, b_ih,
        nullptr, pxgbase, nullptr, 3 * LDIM, IDIM);

    // ---- Fork: half 0 (rows 0..2047) on stream 0, half 1 on s2 ----
    cudaEventRecord(evF, 0);
    cudaStreamWaitEvent(s2, evF, 0);

    for (int hf = 0; hf < 2; hf++) {
        cudaStream_t st = (hf == 0) ? (cudaStream_t)0 : s2;
        const size_t R0 = (size_t)hf * HB;

        __half* ans16_h = pans16 + R0 * ODIM;
        __half* xg_h    = pxg + R0 * 3 * LDIM;
        float*  xgb_h   = pxgbase + R0 * 3 * LDIM;
        __half* h12_h   = ph1216 + R0 * H12;
        __half* s16A_h  = ps16A + R0 * LDIM;
        __half* s16B_h  = ps16B + R0 * LDIM;
        float*  sA_h    = psA + R0 * LDIM;
        float*  sB_h    = psB + R0 * LDIM;

        for (int s = 0; s < OUTER; s++) {
            // xg = xg_base + ans @ W_ih[:, IDIM:]^T   [HB, 3L] fp16
            hgemm<2, 4, 4, 2, 0, 1, 0, 1>
                <<<dim3((3 * LDIM) / 128, HB / 128), 256, SMB, st>>>(
                ans16_h, ODIM, ODIM, ans16_h, ODIM, pwih + IDIM, pwih + IDIM,
                JDIM, 3 * LDIM, nullptr, nullptr, xgb_h, nullptr, xg_h,
                3 * LDIM, ODIM);

            // 4x fused GRU GEMM, ping-pong state A->B->A->B->A (ends in A)
            for (int i = 0; i < INNER; i++) {
                const bool even = (i & 1) == 0;
                gru_gemm<<<dim3(LDIM / 32, HB / 128), 256, SMG, st>>>(
                    b_hh, xg_h,
                    even ? s16A_h : s16B_h, even ? sA_h : sB_h,
                    even ? s16B_h : s16A_h, even ? sB_h : sA_h);
            }

            // h12 = relu(concat(state, ans) @ [aw1; hw1]^T + [ab1; hb1])  fp16
            hgemm<2, 4, 4, 2, 0, 1, 1, 0>
                <<<dim3(H12 / 128, HB / 128), 256, SMB, st>>>(
                s16A_h, LDIM, LDIM, ans16_h, ODIM, paw1, phw1, JDIM, HDIM,
                ab1, hb1, nullptr, nullptr, h12_h, H12, JDIM);

            // logits -> out (fp32); ans16 = half(tanh(logits))
            hgemm<4, 2, 2, 4, 1, 1, 2, 0>
                <<<dim3(ODIM / 128, HB / 128), 256, SMB, st>>>(
                h12_h, H12, HDIM, h12_h, H12, paw2, paw2, HDIM, ODIM,
                ab2, ab2, nullptr,
                ans_out + (size_t)s * BATCH * ODIM + R0 * ODIM,
                ans16_h, ODIM, HDIM);

            // halt = h2 @ hw2^T + hb2
            halt_kernel<<<HB / 8, 256, 0, st>>>(
                h12_h, hw2, hb2, halt_out + (size_t)s * BATCH * 2 + R0 * 2);
        }
    }

    // ---- Join ----
    cudaEventRecord(evJ, s2);
    cudaStreamWaitEvent((cudaStream_t)0, evJ, 0);
}

// round 14
// speedup vs baseline: 1.2250x; 1.0330x over previous
#include <cuda_runtime.h>
#include <cuda_fp16.h>
#include <cstdint>
#include <math.h>

#define BATCH   4096
#define IDIM    1024
#define LDIM    1024
#define HDIM    2048
#define ODIM    512
#define HALTH   1024
#define OUTER   8
#define INNER   4
#define JDIM    (LDIM + ODIM)    // 1536
#define H12     (HDIM + HALTH)   // 3072
#define NSTR    4                // independent batch chains
#define HB      (BATCH / NSTR)   // 1024 rows per chain

// ---------------------------------------------------------------------------
// Device-global scratch (no allocation allowed)
// ---------------------------------------------------------------------------
__device__ float  g_stateA[BATCH * LDIM];
__device__ float  g_stateB[BATCH * LDIM];
__device__ float  g_xgbase[BATCH * 3 * LDIM];

__device__ __half g_xg16[BATCH * 3 * LDIM];
__device__ __half g_h1216[BATCH * H12];      // [h1 (2048) | h2 (1024)] per row

__device__ __half g_state16A[BATCH * LDIM];
__device__ __half g_state16B[BATCH * LDIM];
__device__ __half g_ans16[BATCH * ODIM];
__device__ __half g_in16[BATCH * IDIM];

__device__ __half g_wih16[3 * LDIM * JDIM];
__device__ __half g_whh16[3 * LDIM * LDIM];
__device__ __half g_aw116[HDIM * JDIM];
__device__ __half g_aw216[ODIM * HDIM];
__device__ __half g_hw116[HALTH * JDIM];

__device__ __forceinline__ uint32_t smem_u32(const void* p) {
    uint32_t a;
    asm("{ .reg .u64 t; cvta.to.shared.u64 t, %1; cvt.u32.u64 %0, t; }" : "=r"(a) : "l"(p));
    return a;
}

// Swizzled smem layout: rows of 32 halves (64B) packed into 128B lines.
// Conflict-free for cp.async fill and ldmatrix reads (validated rounds 4-13).
__device__ __forceinline__ uint32_t soff(int r, int c) {
    return (uint32_t)((((r >> 1) * 8) + ((((r & 1) << 2) | c) ^ ((r >> 1) & 7))) << 4);
}

// ---------------------------------------------------------------------------
// Generic fp16 tensor-core GEMM (256 threads, 2 CTAs/SM, BK=32, 4 stages):
//   C = act( concat(A1,A2) @ concatN(W1,W2)^T + biasSel|C0 )
// ---------------------------------------------------------------------------
template <int WM, int WN, int MI, int NG, int W32, int W16, int ACT, int ADDC>
__global__ void __launch_bounds__(WM * WN * 32, 2)
hgemm(const __half* __restrict__ A1, int lda1, int K1,
      const __half* __restrict__ A2, int lda2,
      const __half* __restrict__ W1, const __half* __restrict__ W2,
      int ldw, int nsplit,
      const float* __restrict__ bias1, const float* __restrict__ bias2,
      const float* __restrict__ C0,
      float* __restrict__ C,
      __half* __restrict__ C2,
      int N, int K)
{
    constexpr int THREADS = WM * WN * 32;
    constexpr int BM      = WM * MI * 16;
    constexpr int BN      = WN * NG * 16;
    constexpr int NI      = 2 * NG;
    constexpr int STAGE   = (BM + BN) * 64;
    constexpr int NLOAD   = (BM + BN) * 4 / THREADS;

    extern __shared__ __align__(128) char smem[];
    const uint32_t sb = smem_u32(smem);

    const int tid  = threadIdx.x;
    const int lane = tid & 31;
    const int warp = tid >> 5;
    const int wm   = warp / WN;
    const int wn   = warp % WN;
    const int row0 = blockIdx.y * BM;
    const int col0 = blockIdx.x * BN;

    float c[MI][NI][4];
#pragma unroll
    for (int i = 0; i < MI; i++)
#pragma unroll
        for (int j = 0; j < NI; j++)
#pragma unroll
            for (int k = 0; k < 4; k++) c[i][j][k] = 0.0f;

    const int nc = K >> 5;

    auto load_chunk = [&](int t) {
        const int st = t & 3;
        const int k0 = t << 5;
        const __half* Ab;
        int lda;
        if (k0 < K1) { Ab = A1 + k0;        lda = lda1; }
        else         { Ab = A2 + (k0 - K1); lda = lda2; }
        const uint32_t aB = sb + st * STAGE;
        const uint32_t bB = aB + BM * 64;
#pragma unroll
        for (int j = 0; j < NLOAD; j++) {
            const int idx = j * THREADS + tid;
            if (idx < BM * 4) {
                const int r = idx >> 2, cc = idx & 3;
                const uint32_t d = aB + soff(r, cc);
                const __half* g = Ab + (size_t)(row0 + r) * lda + cc * 8;
                asm volatile("cp.async.cg.shared.global [%0], [%1], 16;" :: "r"(d), "l"(g));
            } else {
                const int li = idx - BM * 4;
                const int r = li >> 2, cc = li & 3;
                const int wr = col0 + r;
                const __half* wbase = (wr < nsplit) ? (W1 + (size_t)wr * ldw)
                                                    : (W2 + (size_t)(wr - nsplit) * ldw);
                const uint32_t d = bB + soff(r, cc);
                asm volatile("cp.async.cg.shared.global [%0], [%1], 16;"
                             :: "r"(d), "l"(wbase + k0 + cc * 8));
            }
        }
        asm volatile("cp.async.commit_group;");
    };

    load_chunk(0);
    load_chunk(1);
    load_chunk(2);

    for (int t = 0; t < nc; t++) {
        if (t + 3 <= nc) asm volatile("cp.async.wait_group 2;");
        else             asm volatile("cp.async.wait_group 0;");
        __syncthreads();
        if (t + 3 < nc) load_chunk(t + 3);

        const uint32_t aB = sb + (t & 3) * STAGE;
        const uint32_t bB = aB + BM * 64;

#pragma unroll
        for (int kh = 0; kh < 2; kh++) {
            uint32_t a[MI][4];
#pragma unroll
            for (int mi = 0; mi < MI; mi++) {
                const int row = wm * (16 * MI) + mi * 16 + (lane & 15);
                const int cc  = kh * 2 + (lane >> 4);
                asm volatile("ldmatrix.sync.aligned.m8n8.x4.shared.b16 {%0,%1,%2,%3}, [%4];"
                             : "=r"(a[mi][0]), "=r"(a[mi][1]), "=r"(a[mi][2]), "=r"(a[mi][3])
                             : "r"(aB + soff(row, cc)));
            }
            uint32_t b[NG][4];
#pragma unroll
            for (int ng = 0; ng < NG; ng++) {
                const int row = wn * (16 * NG) + ng * 16 + (lane & 7) + ((lane >> 4) << 3);
                const int cc  = kh * 2 + ((lane >> 3) & 1);
                asm volatile("ldmatrix.sync.aligned.m8n8.x4.shared.b16 {%0,%1,%2,%3}, [%4];"
                             : "=r"(b[ng][0]), "=r"(b[ng][1]), "=r"(b[ng][2]), "=r"(b[ng][3])
                             : "r"(bB + soff(row, cc)));
            }
#pragma unroll
            for (int mi = 0; mi < MI; mi++)
#pragma unroll
                for (int ng = 0; ng < NG; ng++) {
                    asm volatile(
                        "mma.sync.aligned.m16n8k16.row.col.f32.f16.f16.f32 "
                        "{%0,%1,%2,%3},{%4,%5,%6,%7},{%8,%9},{%0,%1,%2,%3};"
                        : "+f"(c[mi][2 * ng][0]), "+f"(c[mi][2 * ng][1]),
                          "+f"(c[mi][2 * ng][2]), "+f"(c[mi][2 * ng][3])
                        : "r"(a[mi][0]), "r"(a[mi][1]), "r"(a[mi][2]), "r"(a[mi][3]),
                          "r"(b[ng][0]), "r"(b[ng][1]));
                    asm volatile(
                        "mma.sync.aligned.m16n8k16.row.col.f32.f16.f16.f32 "
                        "{%0,%1,%2,%3},{%4,%5,%6,%7},{%8,%9},{%0,%1,%2,%3};"
                        : "+f"(c[mi][2 * ng + 1][0]), "+f"(c[mi][2 * ng + 1][1]),
                          "+f"(c[mi][2 * ng + 1][2]), "+f"(c[mi][2 * ng + 1][3])
                        : "r"(a[mi][0]), "r"(a[mi][1]), "r"(a[mi][2]), "r"(a[mi][3]),
                          "r"(b[ng][2]), "r"(b[ng][3]));
                }
        }
    }

    // Epilogue
#pragma unroll
    for (int mi = 0; mi < MI; mi++) {
        const int r0 = row0 + wm * (16 * MI) + mi * 16 + (lane >> 2);
#pragma unroll
        for (int ni = 0; ni < NI; ni++) {
            const int col = col0 + wn * (16 * NG) + ni * 8 + (lane & 3) * 2;
            const size_t i0 = (size_t)r0 * N + col;
            const size_t i1 = (size_t)(r0 + 8) * N + col;
            float v00, v01, v10, v11;
            if (ADDC) {
                const float2 a0 = *(const float2*)&C0[i0];
                const float2 a1 = *(const float2*)&C0[i1];
                v00 = c[mi][ni][0] + a0.x; v01 = c[mi][ni][1] + a0.y;
                v10 = c[mi][ni][2] + a1.x; v11 = c[mi][ni][3] + a1.y;
            } else {
                const float* bp = (col < nsplit) ? (bias1 + col) : (bias2 + col - nsplit);
                const float b0 = __ldg(bp);
                const float b1 = __ldg(bp + 1);
                v00 = c[mi][ni][0] + b0; v01 = c[mi][ni][1] + b1;
                v10 = c[mi][ni][2] + b0; v11 = c[mi][ni][3] + b1;
            }
            if (ACT == 1) {
                v00 = fmaxf(v00, 0.0f); v01 = fmaxf(v01, 0.0f);
                v10 = fmaxf(v10, 0.0f); v11 = fmaxf(v11, 0.0f);
            }
            if (W32) {
                C[i0] = v00; C[i0 + 1] = v01;
                C[i1] = v10; C[i1 + 1] = v11;
            }
            if (W16) {
                float w00 = v00, w01 = v01, w10 = v10, w11 = v11;
                if (ACT == 2) {
                    w00 = tanhf(v00); w01 = tanhf(v01);
                    w10 = tanhf(v10); w11 = tanhf(v11);
                }
                *(__half2*)&C2[i0] = __floats2half2_rn(w00, w01);
                *(__half2*)&C2[i1] = __floats2half2_rn(w10, w11);
            }
        }
    }
}

// ---------------------------------------------------------------------------
// Fused GRU GEMM, double-buffered state, 256 threads, 2 CTAs/SM, 4 stages.
// BM=128 (WM=4, MI=2), BN=96 = 3 gates x 32 j's (WN=2, NG=3).
// Gate interleave: B-tile row rb -> weight row gate*L + j; accumulators
// (p, 2+p, 4+p) hold (r,z,n) of the same j. xg passed as pointer (row-offset).
// ---------------------------------------------------------------------------
__global__ void __launch_bounds__(256, 2)
gru_gemm(const float* __restrict__ bhh,
         const __half* __restrict__ xg,
         const __half* __restrict__ s16in,
         const float* __restrict__ s32in,
         __half* __restrict__ s16out,
         float* __restrict__ s32out)
{
    constexpr int STAGE = (128 + 96) * 64;   // 14336 B

    extern __shared__ __align__(128) char smem[];
    const uint32_t sb = smem_u32(smem);

    const int tid  = threadIdx.x;
    const int lane = tid & 31;
    const int warp = tid >> 5;
    const int wm   = warp >> 1;   // 0..3
    const int wn   = warp & 1;    // 0..1
    const int row0 = blockIdx.y * 128;
    const int c0j  = blockIdx.x * 32;  // 32 j's per CTA

    float c[2][6][4];
#pragma unroll
    for (int i = 0; i < 2; i++)
#pragma unroll
        for (int j = 0; j < 6; j++)
#pragma unroll
            for (int k = 0; k < 4; k++) c[i][j][k] = 0.0f;

    auto load_chunk = [&](int t) {
        const int st = t & 3;
        const int k0 = t << 5;
        const uint32_t aB = sb + st * STAGE;
        const uint32_t bB = aB + 128 * 64;
#pragma unroll
        for (int j = 0; j < 4; j++) {
            const int idx = j * 256 + tid;
            if (idx < 512) {                       // A: 128 rows x 4 chunks
                const int r = idx >> 2, cc = idx & 3;
                const uint32_t d = aB + soff(r, cc);
                const __half* g = s16in + (size_t)(row0 + r) * LDIM + k0 + cc * 8;
                asm volatile("cp.async.cg.shared.global [%0], [%1], 16;" :: "r"(d), "l"(g));
            } else if (idx < 512 + 384) {          // B: 96 rows x 4 chunks
                const int li = idx - 512;
                const int rb = li >> 2, cc = li & 3;
                const int within = rb % 48;
                const int wrow = (within >> 4) * LDIM + c0j + (rb / 48) * 16 + (within & 15);
                const uint32_t d = bB + soff(rb, cc);
                const __half* g = g_whh16 + (size_t)wrow * LDIM + k0 + cc * 8;
                asm volatile("cp.async.cg.shared.global [%0], [%1], 16;" :: "r"(d), "l"(g));
            }
        }
        asm volatile("cp.async.commit_group;");
    };

    load_chunk(0);
    load_chunk(1);
    load_chunk(2);

    const int nc = LDIM >> 5;  // 32
    for (int t = 0; t < nc; t++) {
        if (t + 3 <= nc) asm volatile("cp.async.wait_group 2;");
        else             asm volatile("cp.async.wait_group 0;");
        __syncthreads();
        if (t + 3 < nc) load_chunk(t + 3);

        const uint32_t aB = sb + (t & 3) * STAGE;
        const uint32_t bB = aB + 128 * 64;

#pragma unroll
        for (int kh = 0; kh < 2; kh++) {
            uint32_t a[2][4];
#pragma unroll
            for (int mi = 0; mi < 2; mi++) {
                const int row = wm * 32 + mi * 16 + (lane & 15);
                const int cc  = kh * 2 + (lane >> 4);
                asm volatile("ldmatrix.sync.aligned.m8n8.x4.shared.b16 {%0,%1,%2,%3}, [%4];"
                             : "=r"(a[mi][0]), "=r"(a[mi][1]), "=r"(a[mi][2]), "=r"(a[mi][3])
                             : "r"(aB + soff(row, cc)));
            }
            uint32_t b[3][4];
#pragma unroll
            for (int ng = 0; ng < 3; ng++) {
                const int row = wn * 48 + ng * 16 + (lane & 7) + ((lane >> 4) << 3);
                const int cc  = kh * 2 + ((lane >> 3) & 1);
                asm volatile("ldmatrix.sync.aligned.m8n8.x4.shared.b16 {%0,%1,%2,%3}, [%4];"
                             : "=r"(b[ng][0]), "=r"(b[ng][1]), "=r"(b[ng][2]), "=r"(b[ng][3])
                             : "r"(bB + soff(row, cc)));
            }
#pragma unroll
            for (int mi = 0; mi < 2; mi++)
#pragma unroll
                for (int ng = 0; ng < 3; ng++) {
                    asm volatile(
                        "mma.sync.aligned.m16n8k16.row.col.f32.f16.f16.f32 "
                        "{%0,%1,%2,%3},{%4,%5,%6,%7},{%8,%9},{%0,%1,%2,%3};"
                        : "+f"(c[mi][2 * ng][0]), "+f"(c[mi][2 * ng][1]),
                          "+f"(c[mi][2 * ng][2]), "+f"(c[mi][2 * ng][3])
                        : "r"(a[mi][0]), "r"(a[mi][1]), "r"(a[mi][2]), "r"(a[mi][3]),
                          "r"(b[ng][0]), "r"(b[ng][1]));
                    asm volatile(
                        "mma.sync.aligned.m16n8k16.row.col.f32.f16.f16.f32 "
                        "{%0,%1,%2,%3},{%4,%5,%6,%7},{%8,%9},{%0,%1,%2,%3};"
                        : "+f"(c[mi][2 * ng + 1][0]), "+f"(c[mi][2 * ng + 1][1]),
                          "+f"(c[mi][2 * ng + 1][2]), "+f"(c[mi][2 * ng + 1][3])
                        : "r"(a[mi][0]), "r"(a[mi][1]), "r"(a[mi][2]), "r"(a[mi][3]),
                          "r"(b[ng][2]), "r"(b[ng][3]));
                }
        }
    }

    // Fused GRU epilogue: warp-tile cols = [r 0..15 | z 16..31 | n 32..47]
#pragma unroll
    for (int mi = 0; mi < 2; mi++) {
        const int r0 = row0 + wm * 32 + mi * 16 + (lane >> 2);
#pragma unroll
        for (int p = 0; p < 2; p++) {
            const int j0 = c0j + wn * 16 + p * 8 + (lane & 3) * 2;
            const float2 br = *(const float2*)&bhh[j0];
            const float2 bz = *(const float2*)&bhh[LDIM + j0];
            const float2 bn = *(const float2*)&bhh[2 * LDIM + j0];
            const float* cr = c[mi][p];
            const float* cz = c[mi][2 + p];
            const float* cn = c[mi][4 + p];
#pragma unroll
            for (int h = 0; h < 2; h++) {
                const int row = r0 + h * 8;
                const float hr0 = cr[2 * h] + br.x, hr1 = cr[2 * h + 1] + br.y;
                const float hz0 = cz[2 * h] + bz.x, hz1 = cz[2 * h + 1] + bz.y;
                const float hn0 = cn[2 * h] + bn.x, hn1 = cn[2 * h + 1] + bn.y;
                const size_t xb = (size_t)row * (3 * LDIM) + j0;
                const float2 xr = __half22float2(*(const __half2*)&xg[xb]);
                const float2 xz = __half22float2(*(const __half2*)&xg[xb + LDIM]);
                const float2 xn = __half22float2(*(const __half2*)&xg[xb + 2 * LDIM]);
                const size_t si = (size_t)row * LDIM + j0;
                const float2 s = *(const float2*)&s32in[si];

                const float rr0 = 1.0f / (1.0f + expf(-(xr.x + hr0)));
                const float zz0 = 1.0f / (1.0f + expf(-(xz.x + hz0)));
                const float nn0 = tanhf(xn.x + rr0 * hn0);
                const float rr1 = 1.0f / (1.0f + expf(-(xr.y + hr1)));
                const float zz1 = 1.0f / (1.0f + expf(-(xz.y + hz1)));
                const float nn1 = tanhf(xn.y + rr1 * hn1);

                float2 ns;
                ns.x = (1.0f - zz0) * nn0 + zz0 * s.x;
                ns.y = (1.0f - zz1) * nn1 + zz1 * s.y;
                *(float2*)&s32out[si] = ns;
                *(__half2*)&s16out[si] = __floats2half2_rn(ns.x, ns.y);
            }
        }
    }
}

// ---------------------------------------------------------------------------
// One-shot init: fp16 conversions of all params + zero state/ans buffers.
// ---------------------------------------------------------------------------
#define N_IN   (BATCH * IDIM)
#define N_WIH  (3 * LDIM * JDIM)
#define N_WHH  (3 * LDIM * LDIM)
#define N_AW1  (HDIM * JDIM)
#define N_AW2  (ODIM * HDIM)
#define N_HW1  (HALTH * JDIM)
#define N_ZERO (BATCH * LDIM)
#define O1 N_IN
#define O2 (O1 + N_WIH)
#define O3 (O2 + N_WHH)
#define O4 (O3 + N_AW1)
#define O5 (O4 + N_AW2)
#define O6 (O5 + N_HW1)
#define O7 (O6 + N_ZERO)                 // 22020352 = 86017 * 256

__global__ void init_cvt(const float* __restrict__ inputs,
                         const float* __restrict__ W_ih,
                         const float* __restrict__ W_hh,
                         const float* __restrict__ aw1,
                         const float* __restrict__ aw2,
                         const float* __restrict__ hw1)
{
    const int i = blockIdx.x * blockDim.x + threadIdx.x;
    if (i < O1)      g_in16[i]         = __float2half_rn(inputs[i]);
    else if (i < O2) g_wih16[i - O1]   = __float2half_rn(W_ih[i - O1]);
    else if (i < O3) g_whh16[i - O2]   = __float2half_rn(W_hh[i - O2]);
    else if (i < O4) g_aw116[i - O3]   = __float2half_rn(aw1[i - O3]);
    else if (i < O5) g_aw216[i - O4]   = __float2half_rn(aw2[i - O4]);
    else if (i < O6) g_hw116[i - O5]   = __float2half_rn(hw1[i - O5]);
    else {
        const int j = i - O6;
        g_stateA[j]   = 0.0f;
        g_state16A[j] = __ushort_as_half((unsigned short)0);
        if (j < BATCH * ODIM) g_ans16[j] = __ushort_as_half((unsigned short)0);
    }
}

// ---------------------------------------------------------------------------
// Halt head: reads h2 slice of the merged h12 buffer (pointer passed in).
// ---------------------------------------------------------------------------
__global__ void halt_kernel(const __half* __restrict__ h12,
                            const float* __restrict__ hw2,
                            const float* __restrict__ hb2,
                            float* __restrict__ out)
{
    const int row  = blockIdx.x * (blockDim.x >> 5) + (threadIdx.x >> 5);
    const int lane = threadIdx.x & 31;
    const __half2* h = (const __half2*)(h12 + (size_t)row * H12 + HDIM);
    const float2* w0 = (const float2*)hw2;
    const float2* w1 = (const float2*)(hw2 + HALTH);
    float s0 = 0.0f, s1 = 0.0f;
    for (int k = lane; k < HALTH / 2; k += 32) {
        const float2 v  = __half22float2(h[k]);
        const float2 a0 = w0[k];
        const float2 a1 = w1[k];
        s0 += v.x * a0.x + v.y * a0.y;
        s1 += v.x * a1.x + v.y * a1.y;
    }
#pragma unroll
    for (int o = 16; o > 0; o >>= 1) {
        s0 += __shfl_down_sync(0xFFFFFFFFu, s0, o);
        s1 += __shfl_down_sync(0xFFFFFFFFu, s1, o);
    }
    if (lane == 0) {
        out[(size_t)row * 2]     = s0 + hb2[0];
        out[(size_t)row * 2 + 1] = s1 + hb2[1];
    }
}

// ---------------------------------------------------------------------------
// Host orchestration: 4-stream fork over independent batch quarters.
// ---------------------------------------------------------------------------
extern "C" void kernel_launch(void* const* d_in, const int* in_sizes, int n_in,
                              void* d_out, int out_size)
{
    const float* inputs = (const float*)d_in[0];
    const float* W_ih   = (const float*)d_in[1];
    const float* W_hh   = (const float*)d_in[2];
    const float* b_ih   = (const float*)d_in[3];
    const float* b_hh   = (const float*)d_in[4];
    const float* aw1    = (const float*)d_in[5];
    const float* ab1    = (const float*)d_in[6];
    const float* aw2    = (const float*)d_in[7];
    const float* ab2    = (const float*)d_in[8];
    const float* hw1    = (const float*)d_in[9];
    const float* hb1    = (const float*)d_in[10];
    const float* hw2    = (const float*)d_in[11];
    const float* hb2    = (const float*)d_in[12];

    float* out = (float*)d_out;
    float* ans_out  = out;                                  // [8, 4096, 512]
    float* halt_out = out + (size_t)OUTER * BATCH * ODIM;   // [8, 4096, 2]

    float *psA, *psB, *pxgbase;
    __half *ps16A, *ps16B, *pxg, *ph1216, *pans16, *pin16;
    __half *pwih, *pwhh, *paw1, *paw2, *phw1;
    cudaGetSymbolAddress((void**)&psA,     g_stateA);
    cudaGetSymbolAddress((void**)&psB,     g_stateB);
    cudaGetSymbolAddress((void**)&pxgbase, g_xgbase);
    cudaGetSymbolAddress((void**)&pxg,     g_xg16);
    cudaGetSymbolAddress((void**)&ph1216,  g_h1216);
    cudaGetSymbolAddress((void**)&ps16A,   g_state16A);
    cudaGetSymbolAddress((void**)&ps16B,   g_state16B);
    cudaGetSymbolAddress((void**)&pans16,  g_ans16);
    cudaGetSymbolAddress((void**)&pin16,   g_in16);
    cudaGetSymbolAddress((void**)&pwih,    g_wih16);
    cudaGetSymbolAddress((void**)&pwhh,    g_whh16);
    cudaGetSymbolAddress((void**)&paw1,    g_aw116);
    cudaGetSymbolAddress((void**)&paw2,    g_aw216);
    cudaGetSymbolAddress((void**)&phw1,    g_hw116);

    const int SMB = 4 * (128 + 128) * 64;  // 65536 (hgemm configs)
    const int SMG = 4 * (128 + 96) * 64;   // 57344 (fused GRU GEMM)
    cudaFuncSetAttribute(hgemm<2, 4, 4, 2, 1, 0, 0, 0>, cudaFuncAttributeMaxDynamicSharedMemorySize, SMB);
    cudaFuncSetAttribute(hgemm<2, 4, 4, 2, 0, 1, 0, 1>, cudaFuncAttributeMaxDynamicSharedMemorySize, SMB);
    cudaFuncSetAttribute(hgemm<2, 4, 4, 2, 0, 1, 1, 0>, cudaFuncAttributeMaxDynamicSharedMemorySize, SMB);
    cudaFuncSetAttribute(hgemm<4, 2, 2, 4, 1, 1, 2, 0>, cudaFuncAttributeMaxDynamicSharedMemorySize, SMB);
    cudaFuncSetAttribute(gru_gemm, cudaFuncAttributeMaxDynamicSharedMemorySize, SMG);

    // One-time stream/event setup (first call is the uncaptured correctness run;
    // captured calls reuse the same handles -> identical graph every capture).
    static cudaStream_t str[NSTR] = {nullptr, nullptr, nullptr, nullptr};  // [0] unused
    static cudaEvent_t  evF = nullptr;
    static cudaEvent_t  evJ[NSTR] = {nullptr, nullptr, nullptr, nullptr};  // [0] unused
    if (str[1] == nullptr) {
        cudaEventCreateWithFlags(&evF, cudaEventDisableTiming);
        for (int i = 1; i < NSTR; i++) {
            cudaStreamCreateWithFlags(&str[i], cudaStreamNonBlocking);
            cudaEventCreateWithFlags(&evJ[i], cudaEventDisableTiming);
        }
    }

    // ---- Prologue on main (capture-origin) stream ----
    init_cvt<<<O7 / 256, 256>>>(inputs, W_ih, W_hh, aw1, aw2, hw1);

    // xg_base = inputs @ W_ih[:, :IDIM]^T + b_ih   (fp32, full batch, once)
    hgemm<2, 4, 4, 2, 1, 0, 0, 0><<<dim3((3 * LDIM) / 128, BATCH / 128), 256, SMB>>>(
        pin16, IDIM, IDIM, pin16, IDIM, pwih, pwih, JDIM, 3 * LDIM, b_ih, b_ih,
        nullptr, pxgbase, nullptr, 3 * LDIM, IDIM);

    // ---- Fork: quarter hf on stream str[hf] (hf=0 -> default stream) ----
    cudaEventRecord(evF, 0);
    for (int i = 1; i < NSTR; i++) cudaStreamWaitEvent(str[i], evF, 0);

    for (int hf = 0; hf < NSTR; hf++) {
        cudaStream_t st = (hf == 0) ? (cudaStream_t)0 : str[hf];
        const size_t R0 = (size_t)hf * HB;

        __half* ans16_h = pans16 + R0 * ODIM;
        __half* xg_h    = pxg + R0 * 3 * LDIM;
        float*  xgb_h   = pxgbase + R0 * 3 * LDIM;
        __half* h12_h   = ph1216 + R0 * H12;
        __half* s16A_h  = ps16A + R0 * LDIM;
        __half* s16B_h  = ps16B + R0 * LDIM;
        float*  sA_h    = psA + R0 * LDIM;
        float*  sB_h    = psB + R0 * LDIM;

        for (int s = 0; s < OUTER; s++) {
            // xg = xg_base + ans @ W_ih[:, IDIM:]^T   [HB, 3L] fp16
            hgemm<2, 4, 4, 2, 0, 1, 0, 1>
                <<<dim3((3 * LDIM) / 128, HB / 128), 256, SMB, st>>>(
                ans16_h, ODIM, ODIM, ans16_h, ODIM, pwih + IDIM, pwih + IDIM,
                JDIM, 3 * LDIM, nullptr, nullptr, xgb_h, nullptr, xg_h,
                3 * LDIM, ODIM);

            // 4x fused GRU GEMM, ping-pong state A->B->A->B->A (ends in A)
            for (int i = 0; i < INNER; i++) {
                const bool even = (i & 1) == 0;
                gru_gemm<<<dim3(LDIM / 32, HB / 128), 256, SMG, st>>>(
                    b_hh, xg_h,
                    even ? s16A_h : s16B_h, even ? sA_h : sB_h,
                    even ? s16B_h : s16A_h, even ? sB_h : sA_h);
            }

            // h12 = relu(concat(state, ans) @ [aw1; hw1]^T + [ab1; hb1])  fp16
            hgemm<2, 4, 4, 2, 0, 1, 1, 0>
                <<<dim3(H12 / 128, HB / 128), 256, SMB, st>>>(
                s16A_h, LDIM, LDIM, ans16_h, ODIM, paw1, phw1, JDIM, HDIM,
                ab1, hb1, nullptr, nullptr, h12_h, H12, JDIM);

            // logits -> out (fp32); ans16 = half(tanh(logits))
            hgemm<4, 2, 2, 4, 1, 1, 2, 0>
                <<<dim3(ODIM / 128, HB / 128), 256, SMB, st>>>(
                h12_h, H12, HDIM, h12_h, H12, paw2, paw2, HDIM, ODIM,
                ab2, ab2, nullptr,
                ans_out + (size_t)s * BATCH * ODIM + R0 * ODIM,
                ans16_h, ODIM, HDIM);

            // halt = h2 @ hw2^T + hb2
            halt_kernel<<<HB / 8, 256, 0, st>>>(
                h12_h, hw2, hb2, halt_out + (size_t)s * BATCH * 2 + R0 * 2);
        }
    }

    // ---- Join ----
    for (int i = 1; i < NSTR; i++) {
        cudaEventRecord(evJ[i], str[i]);
        cudaStreamWaitEvent((cudaStream_t)0, evJ[i], 0);
    }
}